// round 1
// baseline (speedup 1.0000x reference)
#include <cuda_runtime.h>
#include <cuda_bf16.h>
#include <math.h>

// Problem constants
#define CB 4
#define CL 2048
#define CD 1024
#define CH 16
#define CDh 64
#define CM (CB*CL)          // 8192 rows
#define MDSZ (8388608)      // CM*CD elements per scratch plane

// Scratch: 12 planes of [M, D] fp32 + one [M, 128] lora-hidden buffer.
__device__ float g_scratch[12ull*MDSZ + (size_t)CM*128];

enum { EPI_NONE=0, EPI_TANH=1, EPI_SIG=2, EPI_SIGBIAS=3, EPI_W=4, EPI_VMIX=5 };

__device__ __forceinline__ float sigmoidf_(float x){ return 1.f/(1.f+expf(-x)); }

// C[M,N] = A'[M,K] @ Wt[N,K]^T, where A' optionally applies RWKV token-shift mix:
// A'[m,k] = x[m,k] + (x[m-1,k]-x[m,k])*mix[k]  (x[-1]=0 at sequence starts).
// 64x64x16 tiles, 16x16 threads, 4x4 microtile per thread.
template<int EPI, bool MIXED>
__global__ void gemm_tn(const float* __restrict__ A, const float* __restrict__ Wt,
                        const float* __restrict__ mix, const float* __restrict__ bias,
                        const float* __restrict__ p1, const float* __restrict__ p2,
                        float* __restrict__ C, int M, int N, int K)
{
    __shared__ float As[16][64];
    __shared__ float Bs[16][64];
    int tx = threadIdx.x, ty = threadIdx.y;
    int tid = ty*16 + tx;
    int bm = blockIdx.y*64, bn = blockIdx.x*64;
    int lr = tid >> 2;        // 0..63 (row within tile for loading)
    int lk = (tid & 3) * 4;   // 0,4,8,12 (k within tile, float4)

    float acc[4][4];
    #pragma unroll
    for (int i=0;i<4;i++)
        #pragma unroll
        for (int j=0;j<4;j++) acc[i][j]=0.f;

    for (int k0 = 0; k0 < K; k0 += 16) {
        // Load A tile (apply token-shift mix on the fly if MIXED)
        {
            int m = bm + lr;
            const float* ap = A + (size_t)m*K + k0 + lk;
            float4 av = *(const float4*)ap;
            if (MIXED) {
                float4 xp = make_float4(0.f,0.f,0.f,0.f);
                if (m % CL) xp = *(const float4*)(ap - K);
                float4 mx = *(const float4*)(mix + k0 + lk);
                av.x += (xp.x - av.x)*mx.x;
                av.y += (xp.y - av.y)*mx.y;
                av.z += (xp.z - av.z)*mx.z;
                av.w += (xp.w - av.w)*mx.w;
            }
            As[lk+0][lr]=av.x; As[lk+1][lr]=av.y; As[lk+2][lr]=av.z; As[lk+3][lr]=av.w;
        }
        // Load W tile (guard N for small-rank cases)
        {
            int n = bn + lr;
            float4 wv = make_float4(0.f,0.f,0.f,0.f);
            if (n < N) wv = *(const float4*)(Wt + (size_t)n*K + k0 + lk);
            Bs[lk+0][lr]=wv.x; Bs[lk+1][lr]=wv.y; Bs[lk+2][lr]=wv.z; Bs[lk+3][lr]=wv.w;
        }
        __syncthreads();
        #pragma unroll
        for (int kk=0; kk<16; kk++) {
            float4 a = *(const float4*)&As[kk][ty*4];
            float4 b = *(const float4*)&Bs[kk][tx*4];
            float ar[4] = {a.x,a.y,a.z,a.w};
            float br[4] = {b.x,b.y,b.z,b.w};
            #pragma unroll
            for (int i=0;i<4;i++)
                #pragma unroll
                for (int j=0;j<4;j++)
                    acc[i][j] += ar[i]*br[j];
        }
        __syncthreads();
    }

    #pragma unroll
    for (int i=0;i<4;i++) {
        int m = bm + ty*4 + i;
        #pragma unroll
        for (int j=0;j<4;j++) {
            int n = bn + tx*4 + j;
            if (n >= N) continue;
            float v = acc[i][j];
            size_t idx = (size_t)m*N + n;
            if (EPI == EPI_TANH)        v = tanhf(v);
            else if (EPI == EPI_SIG)    v = sigmoidf_(v);
            else if (EPI == EPI_SIGBIAS)v = sigmoidf_(v + bias[n]);
            else if (EPI == EPI_W)      v = expf(-0.606531f * sigmoidf_(v + bias[n]));
            else if (EPI == EPI_VMIX) {
                float vv = sigmoidf_(v + bias[n]);
                float vr = p1[idx];
                v = vr + (p2[idx] - vr)*vv;
            }
            C[idx] = v;
        }
    }
}

__device__ __forceinline__ float warp_red(float v) {
    #pragma unroll
    for (int s=16; s; s>>=1) v += __shfl_xor_sync(0xffffffffu, v, s);
    return v;
}

// Per (m,h) row (one warp each, 8 warps/block): kk normalization, k modification, b = kk*iclr
__global__ void prep_kernel(const float* __restrict__ kraw, const float* __restrict__ iclr,
                            const float* __restrict__ k_k, const float* __restrict__ k_a,
                            float* __restrict__ kk_out, float* __restrict__ kmod,
                            float* __restrict__ bout)
{
    int warp = threadIdx.x >> 5, lane = threadIdx.x & 31;
    int row = blockIdx.x*8 + warp;            // 0 .. M*H-1
    int m = row >> 4, h = row & 15;
    size_t off = (size_t)m*CD + h*CDh;
    int hh = h*CDh;

    float k1 = kraw[off+lane],     k2 = kraw[off+32+lane];
    float kk1 = k1*k_k[hh+lane],   kk2 = k2*k_k[hh+32+lane];
    float ss = warp_red(kk1*kk1 + kk2*kk2);
    float denom = fmaxf(sqrtf(ss), 1e-7f);
    kk1 /= denom; kk2 /= denom;
    kk_out[off+lane]    = kk1;
    kk_out[off+32+lane] = kk2;

    float i1 = iclr[off+lane], i2 = iclr[off+32+lane];
    kmod[off+lane]    = k1*(1.f + (i1-1.f)*k_a[hh+lane]);
    kmod[off+32+lane] = k2*(1.f + (i2-1.f)*k_a[hh+32+lane]);
    bout[off+lane]    = kk1*i1;
    bout[off+32+lane] = kk2*i2;
}

// WKV7 delta-rule scan. One block per (b,h). 128 threads: thread = (row i, column half).
// Each thread keeps 32 state elements (row i, columns half*32..half*32+31) in registers.
__global__ void scan_kernel(const float* __restrict__ r, const float* __restrict__ w,
                            const float* __restrict__ k, const float* __restrict__ v,
                            const float* __restrict__ kkv, const float* __restrict__ bv,
                            float* __restrict__ y)
{
    int bh = blockIdx.x;
    int b = bh >> 4, h = bh & 15;
    int tid = threadIdx.x;
    int i = tid >> 1, half = tid & 1;
    int j0 = tid & 63, grp = tid >> 6;

    __shared__ float sh[2][6][64];   // 0=r 1=w 2=k 3=v 4=kk 5=b, double buffered
    float4 S[8];
    #pragma unroll
    for (int q=0;q<8;q++) S[q] = make_float4(0.f,0.f,0.f,0.f);

    size_t base = (size_t)b*CL*CD + (size_t)h*CDh;

    for (int t=0; t<CL; t++) {
        int buf = t & 1;
        size_t o = base + (size_t)t*CD + j0;
        if (grp == 0) {
            sh[buf][0][j0] = r[o];
            sh[buf][1][j0] = w[o];
            sh[buf][2][j0] = k[o];
        } else {
            sh[buf][3][j0] = v[o];
            sh[buf][4][j0] = kkv[o];
            sh[buf][5][j0] = bv[o];
        }
        __syncthreads();

        const float4* r4 = (const float4*)&sh[buf][0][half*32];
        const float4* w4 = (const float4*)&sh[buf][1][half*32];
        const float4* k4 = (const float4*)&sh[buf][2][half*32];
        const float4* a4 = (const float4*)&sh[buf][4][half*32];
        const float4* b4 = (const float4*)&sh[buf][5][half*32];
        float vi = sh[buf][3][i];

        // sa_i = sum_j S_ij * a_j,  a = -kk
        float dot = 0.f;
        #pragma unroll
        for (int q=0;q<8;q++) {
            float4 aq = a4[q];
            dot += S[q].x*aq.x + S[q].y*aq.y + S[q].z*aq.z + S[q].w*aq.w;
        }
        dot += __shfl_xor_sync(0xffffffffu, dot, 1);
        float sa = -dot;

        float yl = 0.f;
        #pragma unroll
        for (int q=0;q<8;q++) {
            float4 wq=w4[q], kq=k4[q], bq=b4[q], rq=r4[q];
            S[q].x = S[q].x*wq.x + vi*kq.x + sa*bq.x; yl += S[q].x*rq.x;
            S[q].y = S[q].y*wq.y + vi*kq.y + sa*bq.y; yl += S[q].y*rq.y;
            S[q].z = S[q].z*wq.z + vi*kq.z + sa*bq.z; yl += S[q].z*rq.z;
            S[q].w = S[q].w*wq.w + vi*kq.w + sa*bq.w; yl += S[q].w*rq.w;
        }
        yl += __shfl_xor_sync(0xffffffffu, yl, 1);
        if (half == 0) y[base + (size_t)t*CD + i] = yl;
    }
}

// Per (m,h) row: groupnorm + bonus + gate -> pre-activation for Wo
__global__ void post_kernel(const float* __restrict__ y, const float* __restrict__ r,
                            const float* __restrict__ kmod, const float* __restrict__ vmix,
                            const float* __restrict__ gate, const float* __restrict__ gnw,
                            const float* __restrict__ gnb, const float* __restrict__ r_k,
                            float* __restrict__ pre)
{
    int warp = threadIdx.x >> 5, lane = threadIdx.x & 31;
    int row = blockIdx.x*8 + warp;
    int m = row >> 4, h = row & 15;
    size_t off = (size_t)m*CD + h*CDh;
    int hh = h*CDh;

    float y1 = y[off+lane], y2 = y[off+32+lane];
    float mean = warp_red(y1 + y2) * (1.f/64.f);
    float d1 = y1 - mean, d2 = y2 - mean;
    float var = warp_red(d1*d1 + d2*d2) * (1.f/64.f);
    float inv = 1.f / sqrtf(var + 0.00064f);
    float o1 = gnw[hh+lane]   *d1*inv + gnb[hh+lane];
    float o2 = gnw[hh+32+lane]*d2*inv + gnb[hh+32+lane];

    float bonus = warp_red(r[off+lane]*kmod[off+lane]*r_k[hh+lane]
                         + r[off+32+lane]*kmod[off+32+lane]*r_k[hh+32+lane]);
    o1 += bonus * vmix[off+lane];
    o2 += bonus * vmix[off+32+lane];
    pre[off+lane]    = o1 * gate[off+lane];
    pre[off+32+lane] = o2 * gate[off+32+lane];
}

extern "C" void kernel_launch(void* const* d_in, const int* in_sizes, int n_in,
                              void* d_out, int out_size)
{
    const float* x      = (const float*)d_in[0];
    const float* vfirst = (const float*)d_in[1];
    const float* x_r    = (const float*)d_in[2];
    const float* x_w    = (const float*)d_in[3];
    const float* x_k    = (const float*)d_in[4];
    const float* x_v    = (const float*)d_in[5];
    const float* x_a    = (const float*)d_in[6];
    const float* x_g    = (const float*)d_in[7];
    const float* k_k    = (const float*)d_in[8];
    const float* k_a    = (const float*)d_in[9];
    const float* r_k    = (const float*)d_in[10];
    const float* Wr     = (const float*)d_in[11];
    const float* Wk     = (const float*)d_in[12];
    const float* Wv     = (const float*)d_in[13];
    const float* Wo     = (const float*)d_in[14];
    const float* gnw    = (const float*)d_in[15];
    const float* gnb    = (const float*)d_in[16];
    const float* wA     = (const float*)d_in[17];
    const float* wB     = (const float*)d_in[18];
    const float* wb     = (const float*)d_in[19];
    const float* vA     = (const float*)d_in[20];
    const float* vB     = (const float*)d_in[21];
    const float* vb     = (const float*)d_in[22];
    const float* aA     = (const float*)d_in[23];
    const float* aB     = (const float*)d_in[24];
    const float* ab     = (const float*)d_in[25];
    const float* gA     = (const float*)d_in[26];
    const float* gB     = (const float*)d_in[27];
    float* out = (float*)d_out;

    float* S;
    cudaGetSymbolAddress((void**)&S, g_scratch);
    float* g_r    = S + 0ull*MDSZ;
    float* g_kraw = S + 1ull*MDSZ;
    float* g_vraw = S + 2ull*MDSZ;
    float* g_w    = S + 3ull*MDSZ;
    float* g_iclr = S + 4ull*MDSZ;
    float* g_vmix = S + 5ull*MDSZ;
    float* g_gate = S + 6ull*MDSZ;
    float* g_kk   = S + 7ull*MDSZ;
    float* g_km   = S + 8ull*MDSZ;
    float* g_b    = S + 9ull*MDSZ;
    float* g_y    = S + 10ull*MDSZ;
    float* g_pre  = S + 11ull*MDSZ;
    float* g_h    = S + 12ull*MDSZ;

    dim3 blk(16,16);
    dim3 gD((CD+63)/64, CM/64);
    dim3 g64(1, CM/64);
    dim3 g128(2, CM/64);
    dim3 g32(1, CM/64);

    // Big projections (token-shift fused)
    gemm_tn<EPI_NONE,true><<<gD, blk>>>(x, Wr, x_r, nullptr, nullptr, nullptr, g_r,    CM, CD, CD);
    gemm_tn<EPI_NONE,true><<<gD, blk>>>(x, Wk, x_k, nullptr, nullptr, nullptr, g_kraw, CM, CD, CD);
    gemm_tn<EPI_NONE,true><<<gD, blk>>>(x, Wv, x_v, nullptr, nullptr, nullptr, g_vraw, CM, CD, CD);

    // decay LoRA: w = exp(-0.606531*sigmoid(tanh(xw@wA^T)@wB^T + wb))
    gemm_tn<EPI_TANH,true ><<<g64, blk>>>(x,   wA, x_w, nullptr, nullptr, nullptr, g_h, CM, 64, CD);
    gemm_tn<EPI_W,   false><<<gD,  blk>>>(g_h, wB, nullptr, wb,  nullptr, nullptr, g_w, CM, CD, 64);

    // a LoRA: iclr = sigmoid(xa@aA^T@aB^T + ab)
    gemm_tn<EPI_NONE,true   ><<<g64, blk>>>(x,   aA, x_a, nullptr, nullptr, nullptr, g_h,    CM, 64, CD);
    gemm_tn<EPI_SIGBIAS,false><<<gD, blk>>>(g_h, aB, nullptr, ab,  nullptr, nullptr, g_iclr, CM, CD, 64);

    // v LoRA: vmix = v + (v_first - v)*sigmoid(xv@vA^T@vB^T + vb)
    gemm_tn<EPI_NONE,true ><<<g32, blk>>>(x,   vA, x_v, nullptr, nullptr, nullptr, g_h,    CM, 32, CD);
    gemm_tn<EPI_VMIX,false><<<gD,  blk>>>(g_h, vB, nullptr, vb,  g_vraw, vfirst,  g_vmix, CM, CD, 32);

    // g LoRA: gate = sigmoid(xg@gA^T)@gB^T
    gemm_tn<EPI_SIG, true ><<<g128, blk>>>(x,   gA, x_g, nullptr, nullptr, nullptr, g_h,    CM, 128, CD);
    gemm_tn<EPI_NONE,false><<<gD,   blk>>>(g_h, gB, nullptr, nullptr, nullptr, nullptr, g_gate, CM, CD, 128);

    // kk normalize / k modify / b = kk*iclr
    prep_kernel<<<CM*CH/8, 256>>>(g_kraw, g_iclr, k_k, k_a, g_kk, g_km, g_b);

    // sequential WKV7 scan
    scan_kernel<<<CB*CH, 128>>>(g_r, g_w, g_km, g_vmix, g_kk, g_b, g_y);

    // groupnorm + bonus + gate
    post_kernel<<<CM*CH/8, 256>>>(g_y, g_r, g_km, g_vmix, g_gate, gnw, gnb, r_k, g_pre);

    // output projection
    gemm_tn<EPI_NONE,false><<<gD, blk>>>(g_pre, Wo, nullptr, nullptr, nullptr, nullptr, out, CM, CD, CD);
}

// round 3
// speedup vs baseline: 1.4442x; 1.4442x over previous
#include <cuda_runtime.h>
#include <cuda_bf16.h>
#include <math.h>
#include <stdint.h>

// Problem constants
#define CB 4
#define CL 2048
#define CD 1024
#define CH 16
#define CDh 64
#define CM (CB*CL)          // 8192 rows
#define MDSZ (8388608)      // CM*CD elements per scratch plane

__device__ float g_scratch[12ull*MDSZ + (size_t)CM*128];

enum { EPI_NONE=0, EPI_TANH=1, EPI_SIG=2, EPI_SIGBIAS=3, EPI_W=4, EPI_VMIX=5 };

__device__ __forceinline__ float sigmoidf_(float x){ return 1.f/(1.f+expf(-x)); }

__device__ __forceinline__ uint32_t to_tf32(float f){
    uint32_t u; asm("cvt.rna.tf32.f32 %0, %1;" : "=r"(u) : "f"(f)); return u;
}

__device__ __forceinline__ void mma_tf32(float* c, const uint32_t* a, uint32_t b0, uint32_t b1){
    asm volatile(
        "mma.sync.aligned.m16n8k8.row.col.f32.tf32.tf32.f32 "
        "{%0,%1,%2,%3}, {%4,%5,%6,%7}, {%8,%9}, {%0,%1,%2,%3};"
        : "+f"(c[0]), "+f"(c[1]), "+f"(c[2]), "+f"(c[3])
        : "r"(a[0]), "r"(a[1]), "r"(a[2]), "r"(a[3]), "r"(b0), "r"(b1));
}

// ---------------- tf32 mma.sync GEMM ----------------
// C[M,N] = A'[M,K] @ Wt[N,K]^T  (A' = token-shift mix when MIXED)
// CTA tile 128x128, BK=32. 8 warps as 4(M) x 2(N), warp tile 32x64, m16n8k8.
template<int EPI, bool MIXED>
__global__ void __launch_bounds__(256,2) mma_gemm(
    const float* __restrict__ A, const float* __restrict__ Wt,
    const float* __restrict__ mix, const float* __restrict__ bias,
    const float* __restrict__ p1, const float* __restrict__ p2,
    float* __restrict__ C, int M, int N, int K)
{
    __shared__ uint32_t As[128][36];   // padded: (4r+c) mod 32 distinct -> conflict-free
    __shared__ uint32_t Bs[128][36];

    int tid = threadIdx.x, lane = tid & 31, wid = tid >> 5;
    int bm = blockIdx.y * 128, bn = blockIdx.x * 128;
    int wm = (wid & 3) * 32, wn = (wid >> 2) * 64;

    float acc[2][8][4];
    #pragma unroll
    for (int i=0;i<2;i++)
        #pragma unroll
        for (int j=0;j<8;j++)
            #pragma unroll
            for (int q=0;q<4;q++) acc[i][j][q] = 0.f;

    int nch = K >> 5;
    for (int c = 0; c < nch; c++) {
        int k0 = c << 5;
        __syncthreads();   // previous compute done before overwriting smem
        // ---- fill A and B tiles (each thread: 4 float4 of A, 4 of B) ----
        #pragma unroll
        for (int i = 0; i < 4; i++) {
            int e = i*256 + tid;          // 0..1023
            int row = e >> 3, kp = (e & 7) << 2;
            // A (token-shift mixed, tf32-rounded)
            {
                int m = bm + row;
                const float* ap = A + (size_t)m*K + k0 + kp;
                float4 av = *(const float4*)ap;
                if (MIXED) {
                    float4 xp = make_float4(0.f,0.f,0.f,0.f);
                    if (m % CL) xp = *(const float4*)(ap - K);
                    float4 mx = *(const float4*)(mix + k0 + kp);
                    av.x += (xp.x - av.x)*mx.x;
                    av.y += (xp.y - av.y)*mx.y;
                    av.z += (xp.z - av.z)*mx.z;
                    av.w += (xp.w - av.w)*mx.w;
                }
                uint4 st = make_uint4(to_tf32(av.x), to_tf32(av.y), to_tf32(av.z), to_tf32(av.w));
                *(uint4*)&As[row][kp] = st;
            }
            // B
            {
                int n = bn + row;
                uint4 st = make_uint4(0u,0u,0u,0u);
                if (n < N) {
                    float4 bv = *(const float4*)(Wt + (size_t)n*K + k0 + kp);
                    st = make_uint4(to_tf32(bv.x), to_tf32(bv.y), to_tf32(bv.z), to_tf32(bv.w));
                }
                *(uint4*)&Bs[row][kp] = st;
            }
        }
        __syncthreads();
        // ---- compute: 4 k-steps of 8 ----
        #pragma unroll
        for (int s = 0; s < 4; s++) {
            int ks = (s << 3) + (lane & 3);
            uint32_t a[2][4];
            #pragma unroll
            for (int i = 0; i < 2; i++) {
                int r = wm + i*16 + (lane >> 2);
                a[i][0] = As[r][ks];
                a[i][1] = As[r+8][ks];
                a[i][2] = As[r][ks+4];
                a[i][3] = As[r+8][ks+4];
            }
            #pragma unroll
            for (int j = 0; j < 8; j++) {
                int n = wn + j*8 + (lane >> 2);
                uint32_t b0 = Bs[n][ks], b1 = Bs[n][ks+4];
                mma_tf32(acc[0][j], a[0], b0, b1);
                mma_tf32(acc[1][j], a[1], b0, b1);
            }
        }
    }

    // ---- epilogue ----
    #pragma unroll
    for (int i = 0; i < 2; i++) {
        int r0 = bm + wm + i*16 + (lane >> 2);
        #pragma unroll
        for (int j = 0; j < 8; j++) {
            int col = bn + wn + j*8 + (lane & 3)*2;
            if (col >= N) continue;
            #pragma unroll
            for (int hrow = 0; hrow < 2; hrow++) {
                int m = r0 + hrow*8;
                size_t idx = (size_t)m*N + col;
                float v0 = acc[i][j][hrow*2+0];
                float v1 = acc[i][j][hrow*2+1];
                if (EPI == EPI_TANH) { v0 = tanhf(v0); v1 = tanhf(v1); }
                else if (EPI == EPI_SIG) { v0 = sigmoidf_(v0); v1 = sigmoidf_(v1); }
                else if (EPI == EPI_SIGBIAS) {
                    v0 = sigmoidf_(v0 + bias[col]); v1 = sigmoidf_(v1 + bias[col+1]);
                } else if (EPI == EPI_W) {
                    v0 = expf(-0.606531f * sigmoidf_(v0 + bias[col]));
                    v1 = expf(-0.606531f * sigmoidf_(v1 + bias[col+1]));
                } else if (EPI == EPI_VMIX) {
                    float s0 = sigmoidf_(v0 + bias[col]), s1 = sigmoidf_(v1 + bias[col+1]);
                    float2 vr = *(const float2*)(p1 + idx);
                    float2 vf = *(const float2*)(p2 + idx);
                    v0 = vr.x + (vf.x - vr.x)*s0;
                    v1 = vr.y + (vf.y - vr.y)*s1;
                }
                float2 o = make_float2(v0, v1);
                *(float2*)(C + idx) = o;
            }
        }
    }
}

// ---------------- elementwise kernels ----------------
__device__ __forceinline__ float warp_red(float v) {
    #pragma unroll
    for (int s=16; s; s>>=1) v += __shfl_xor_sync(0xffffffffu, v, s);
    return v;
}

__global__ void prep_kernel(const float* __restrict__ kraw, const float* __restrict__ iclr,
                            const float* __restrict__ k_k, const float* __restrict__ k_a,
                            float* __restrict__ kk_out, float* __restrict__ kmod,
                            float* __restrict__ bout)
{
    int warp = threadIdx.x >> 5, lane = threadIdx.x & 31;
    int row = blockIdx.x*8 + warp;
    int m = row >> 4, h = row & 15;
    size_t off = (size_t)m*CD + h*CDh;
    int hh = h*CDh;

    float k1 = kraw[off+lane],     k2 = kraw[off+32+lane];
    float kk1 = k1*k_k[hh+lane],   kk2 = k2*k_k[hh+32+lane];
    float ss = warp_red(kk1*kk1 + kk2*kk2);
    float denom = fmaxf(sqrtf(ss), 1e-7f);
    kk1 /= denom; kk2 /= denom;
    kk_out[off+lane]    = kk1;
    kk_out[off+32+lane] = kk2;

    float i1 = iclr[off+lane], i2 = iclr[off+32+lane];
    kmod[off+lane]    = k1*(1.f + (i1-1.f)*k_a[hh+lane]);
    kmod[off+32+lane] = k2*(1.f + (i2-1.f)*k_a[hh+32+lane]);
    bout[off+lane]    = kk1*i1;
    bout[off+32+lane] = kk2*i2;
}

// WKV7 scan with 2-deep register prefetch.
__global__ void __launch_bounds__(128,1) scan_kernel(
    const float* __restrict__ r, const float* __restrict__ w,
    const float* __restrict__ k, const float* __restrict__ v,
    const float* __restrict__ kkv, const float* __restrict__ bv,
    float* __restrict__ y)
{
    int bh = blockIdx.x;
    int b = bh >> 4, h = bh & 15;
    int tid = threadIdx.x;
    int i = tid >> 1, half = tid & 1;
    int j0 = tid & 63, grp = tid >> 6;

    __shared__ float sh[2][6][64];
    float4 S[8];
    #pragma unroll
    for (int q=0;q<8;q++) S[q] = make_float4(0.f,0.f,0.f,0.f);

    size_t base = (size_t)b*CL*CD + (size_t)h*CDh;

    float pf[2][3];
    {
        size_t o0 = base + j0, o1 = base + CD + j0;
        if (grp == 0) {
            pf[0][0]=r[o0]; pf[0][1]=w[o0]; pf[0][2]=k[o0];
            pf[1][0]=r[o1]; pf[1][1]=w[o1]; pf[1][2]=k[o1];
        } else {
            pf[0][0]=v[o0]; pf[0][1]=kkv[o0]; pf[0][2]=bv[o0];
            pf[1][0]=v[o1]; pf[1][1]=kkv[o1]; pf[1][2]=bv[o1];
        }
    }

    for (int t=0; t<CL; t++) {
        int s = t & 1;
        if (grp == 0) {
            sh[s][0][j0]=pf[s][0]; sh[s][1][j0]=pf[s][1]; sh[s][2][j0]=pf[s][2];
        } else {
            sh[s][3][j0]=pf[s][0]; sh[s][4][j0]=pf[s][1]; sh[s][5][j0]=pf[s][2];
        }
        __syncthreads();
        if (t + 2 < CL) {
            size_t o = base + (size_t)(t+2)*CD + j0;
            if (grp == 0) { pf[s][0]=r[o]; pf[s][1]=w[o]; pf[s][2]=k[o]; }
            else          { pf[s][0]=v[o]; pf[s][1]=kkv[o]; pf[s][2]=bv[o]; }
        }

        const float4* r4 = (const float4*)&sh[s][0][half*32];
        const float4* w4 = (const float4*)&sh[s][1][half*32];
        const float4* k4 = (const float4*)&sh[s][2][half*32];
        const float4* a4 = (const float4*)&sh[s][4][half*32];
        const float4* b4 = (const float4*)&sh[s][5][half*32];
        float vi = sh[s][3][i];

        float dot = 0.f;
        #pragma unroll
        for (int q=0;q<8;q++) {
            float4 aq = a4[q];
            dot += S[q].x*aq.x + S[q].y*aq.y + S[q].z*aq.z + S[q].w*aq.w;
        }
        dot += __shfl_xor_sync(0xffffffffu, dot, 1);
        float sa = -dot;

        float yl = 0.f;
        #pragma unroll
        for (int q=0;q<8;q++) {
            float4 wq=w4[q], kq=k4[q], bq=b4[q], rq=r4[q];
            S[q].x = S[q].x*wq.x + vi*kq.x + sa*bq.x; yl += S[q].x*rq.x;
            S[q].y = S[q].y*wq.y + vi*kq.y + sa*bq.y; yl += S[q].y*rq.y;
            S[q].z = S[q].z*wq.z + vi*kq.z + sa*bq.z; yl += S[q].z*rq.z;
            S[q].w = S[q].w*wq.w + vi*kq.w + sa*bq.w; yl += S[q].w*rq.w;
        }
        yl += __shfl_xor_sync(0xffffffffu, yl, 1);
        if (half == 0) y[base + (size_t)t*CD + i] = yl;
    }
}

__global__ void post_kernel(const float* __restrict__ y, const float* __restrict__ r,
                            const float* __restrict__ kmod, const float* __restrict__ vmix,
                            const float* __restrict__ gate, const float* __restrict__ gnw,
                            const float* __restrict__ gnb, const float* __restrict__ r_k,
                            float* __restrict__ pre)
{
    int warp = threadIdx.x >> 5, lane = threadIdx.x & 31;
    int row = blockIdx.x*8 + warp;
    int m = row >> 4, h = row & 15;
    size_t off = (size_t)m*CD + h*CDh;
    int hh = h*CDh;

    float y1 = y[off+lane], y2 = y[off+32+lane];
    float mean = warp_red(y1 + y2) * (1.f/64.f);
    float d1 = y1 - mean, d2 = y2 - mean;
    float var = warp_red(d1*d1 + d2*d2) * (1.f/64.f);
    float inv = 1.f / sqrtf(var + 0.00064f);
    float o1 = gnw[hh+lane]   *d1*inv + gnb[hh+lane];
    float o2 = gnw[hh+32+lane]*d2*inv + gnb[hh+32+lane];

    float bonus = warp_red(r[off+lane]*kmod[off+lane]*r_k[hh+lane]
                         + r[off+32+lane]*kmod[off+32+lane]*r_k[hh+32+lane]);
    o1 += bonus * vmix[off+lane];
    o2 += bonus * vmix[off+32+lane];
    pre[off+lane]    = o1 * gate[off+lane];
    pre[off+32+lane] = o2 * gate[off+32+lane];
}

// ---------------- host ----------------
extern "C" void kernel_launch(void* const* d_in, const int* in_sizes, int n_in,
                              void* d_out, int out_size)
{
    const float* x      = (const float*)d_in[0];
    const float* vfirst = (const float*)d_in[1];
    const float* x_r    = (const float*)d_in[2];
    const float* x_w    = (const float*)d_in[3];
    const float* x_k    = (const float*)d_in[4];
    const float* x_v    = (const float*)d_in[5];
    const float* x_a    = (const float*)d_in[6];
    const float* x_g    = (const float*)d_in[7];
    const float* k_k    = (const float*)d_in[8];
    const float* k_a    = (const float*)d_in[9];
    const float* r_k    = (const float*)d_in[10];
    const float* Wr     = (const float*)d_in[11];
    const float* Wk     = (const float*)d_in[12];
    const float* Wv     = (const float*)d_in[13];
    const float* Wo     = (const float*)d_in[14];
    const float* gnw    = (const float*)d_in[15];
    const float* gnb    = (const float*)d_in[16];
    const float* wA     = (const float*)d_in[17];
    const float* wB     = (const float*)d_in[18];
    const float* wb     = (const float*)d_in[19];
    const float* vA     = (const float*)d_in[20];
    const float* vB     = (const float*)d_in[21];
    const float* vb     = (const float*)d_in[22];
    const float* aA     = (const float*)d_in[23];
    const float* aB     = (const float*)d_in[24];
    const float* ab     = (const float*)d_in[25];
    const float* gA     = (const float*)d_in[26];
    const float* gB     = (const float*)d_in[27];
    float* out = (float*)d_out;

    float* S;
    cudaGetSymbolAddress((void**)&S, g_scratch);
    float* g_r    = S + 0ull*MDSZ;
    float* g_kraw = S + 1ull*MDSZ;
    float* g_vraw = S + 2ull*MDSZ;
    float* g_w    = S + 3ull*MDSZ;
    float* g_iclr = S + 4ull*MDSZ;
    float* g_vmix = S + 5ull*MDSZ;
    float* g_gate = S + 6ull*MDSZ;
    float* g_kk   = S + 7ull*MDSZ;
    float* g_km   = S + 8ull*MDSZ;
    float* g_b    = S + 9ull*MDSZ;
    float* g_y    = S + 10ull*MDSZ;
    float* g_pre  = S + 11ull*MDSZ;
    float* g_h    = S + 12ull*MDSZ;

    dim3 blk(256);
    dim3 gBig(CD/128, CM/128);   // (8, 64)
    dim3 gOne(1, CM/128);        // (1, 64)

    // Big projections (token-shift fused)
    mma_gemm<EPI_NONE,true><<<gBig, blk>>>(x, Wr, x_r, nullptr, nullptr, nullptr, g_r,    CM, CD, CD);
    mma_gemm<EPI_NONE,true><<<gBig, blk>>>(x, Wk, x_k, nullptr, nullptr, nullptr, g_kraw, CM, CD, CD);
    mma_gemm<EPI_NONE,true><<<gBig, blk>>>(x, Wv, x_v, nullptr, nullptr, nullptr, g_vraw, CM, CD, CD);

    // decay LoRA: w = exp(-0.606531*sigmoid(tanh(xw@wA^T)@wB^T + wb))
    mma_gemm<EPI_TANH,true><<<gOne, blk>>>(x,   wA, x_w, nullptr, nullptr, nullptr, g_h, CM, 64, CD);
    mma_gemm<EPI_W,false><<<gBig, blk>>>(g_h, wB, nullptr, wb,  nullptr, nullptr, g_w, CM, CD, 64);

    // a LoRA: iclr = sigmoid(xa@aA^T@aB^T + ab)
    mma_gemm<EPI_NONE,true><<<gOne, blk>>>(x,   aA, x_a, nullptr, nullptr, nullptr, g_h,    CM, 64, CD);
    mma_gemm<EPI_SIGBIAS,false><<<gBig, blk>>>(g_h, aB, nullptr, ab, nullptr, nullptr, g_iclr, CM, CD, 64);

    // v LoRA: vmix = v + (v_first - v)*sigmoid(xv@vA^T@vB^T + vb)
    mma_gemm<EPI_NONE,true><<<gOne, blk>>>(x,   vA, x_v, nullptr, nullptr, nullptr, g_h,    CM, 32, CD);
    mma_gemm<EPI_VMIX,false><<<gBig, blk>>>(g_h, vB, nullptr, vb, g_vraw, vfirst, g_vmix, CM, CD, 32);

    // g LoRA: gate = sigmoid(xg@gA^T)@gB^T
    mma_gemm<EPI_SIG,true><<<gOne, blk>>>(x,   gA, x_g, nullptr, nullptr, nullptr, g_h,    CM, 128, CD);
    mma_gemm<EPI_NONE,false><<<gBig, blk>>>(g_h, gB, nullptr, nullptr, nullptr, nullptr, g_gate, CM, CD, 128);

    // kk normalize / k modify / b
    prep_kernel<<<CM*CH/8, 256>>>(g_kraw, g_iclr, k_k, k_a, g_kk, g_km, g_b);

    // sequential WKV7 scan
    scan_kernel<<<CB*CH, 128>>>(g_r, g_w, g_km, g_vmix, g_kk, g_b, g_y);

    // groupnorm + bonus + gate
    post_kernel<<<CM*CH/8, 256>>>(g_y, g_r, g_km, g_vmix, g_gate, gnw, gnb, r_k, g_pre);

    // output projection
    mma_gemm<EPI_NONE,false><<<gBig, blk>>>(g_pre, Wo, nullptr, nullptr, nullptr, nullptr, out, CM, CD, CD);
}

// round 4
// speedup vs baseline: 1.7405x; 1.2051x over previous
#include <cuda_runtime.h>
#include <cuda_bf16.h>
#include <math.h>
#include <stdint.h>

// Problem constants
#define CB 4
#define CL 2048
#define CD 1024
#define CH 16
#define CDh 64
#define CM (CB*CL)          // 8192 rows
#define MDSZ (8388608)      // CM*CD elements per scratch plane

// 20 planes: 0-5 mixed x (xr,xw,xk,xv,xa,xg); 6 r; 7 kraw; 8 vraw; 9 w; 10 iclr;
// 11 vmix; 12 gate; 13 kk; 14 km; 15 b; 16 y; 17 pre; 18 rounded weights; 19 lora hidden
__device__ float g_scratch[20ull*MDSZ];

enum { EPI_NONE=0, EPI_TANH=1, EPI_SIG=2, EPI_SIGBIAS=3, EPI_W=4, EPI_VMIX=5 };

__device__ __forceinline__ float sigmoidf_(float x){ return 1.f/(1.f+expf(-x)); }

__device__ __forceinline__ uint32_t to_tf32(float f){
    uint32_t u; asm("cvt.rna.tf32.f32 %0, %1;" : "=r"(u) : "f"(f)); return u;
}
__device__ __forceinline__ float rnaf(float f){ return __uint_as_float(to_tf32(f)); }

__device__ __forceinline__ void mma_tf32(float* c, const uint32_t* a, uint32_t b0, uint32_t b1){
    asm volatile(
        "mma.sync.aligned.m16n8k8.row.col.f32.tf32.tf32.f32 "
        "{%0,%1,%2,%3}, {%4,%5,%6,%7}, {%8,%9}, {%0,%1,%2,%3};"
        : "+f"(c[0]), "+f"(c[1]), "+f"(c[2]), "+f"(c[3])
        : "r"(a[0]), "r"(a[1]), "r"(a[2]), "r"(a[3]), "r"(b0), "r"(b1));
}

// ---------------- mix + tf32-round: 6 planes from x ----------------
__global__ void __launch_bounds__(256) mix6_kernel(
    const float* __restrict__ x,
    const float* __restrict__ m0, const float* __restrict__ m1,
    const float* __restrict__ m2, const float* __restrict__ m3,
    const float* __restrict__ m4, const float* __restrict__ m5,
    float* __restrict__ o0, float* __restrict__ o1, float* __restrict__ o2,
    float* __restrict__ o3, float* __restrict__ o4, float* __restrict__ o5)
{
    size_t v = (size_t)blockIdx.x*256 + threadIdx.x;   // vec4 id; total CM*CD/4
    int m = (int)(v >> 8);
    int kp = (int)(v & 255) << 2;
    size_t off = (size_t)m*CD + kp;
    float4 xv = *(const float4*)(x + off);
    float4 xp = make_float4(0.f,0.f,0.f,0.f);
    if (m % CL) xp = *(const float4*)(x + off - CD);
    float4 dx = make_float4(xp.x-xv.x, xp.y-xv.y, xp.z-xv.z, xp.w-xv.w);

    #define DO_MIX(MI, OI) { \
        float4 mx = *(const float4*)(MI + kp); \
        float4 r; \
        r.x = rnaf(fmaf(dx.x, mx.x, xv.x)); \
        r.y = rnaf(fmaf(dx.y, mx.y, xv.y)); \
        r.z = rnaf(fmaf(dx.z, mx.z, xv.z)); \
        r.w = rnaf(fmaf(dx.w, mx.w, xv.w)); \
        *(float4*)(OI + off) = r; }
    DO_MIX(m0, o0); DO_MIX(m1, o1); DO_MIX(m2, o2);
    DO_MIX(m3, o3); DO_MIX(m4, o4); DO_MIX(m5, o5);
    #undef DO_MIX
}

// ---------------- round 12 weight buffers ----------------
struct RW12 { const float* s[12]; float* d[12]; int n[12]; };
__global__ void __launch_bounds__(256) roundw_kernel(RW12 w)
{
    int seg = blockIdx.y;
    int n4 = w.n[seg] >> 2;
    const float* s = w.s[seg];
    float* d = w.d[seg];
    for (int v = blockIdx.x*256 + threadIdx.x; v < n4; v += gridDim.x*256) {
        float4 a = *(const float4*)(s + v*4);
        float4 r = make_float4(rnaf(a.x), rnaf(a.y), rnaf(a.z), rnaf(a.w));
        *(float4*)(d + v*4) = r;
    }
}

// ---------------- cp.async double-buffered tf32 GEMM ----------------
// C[M,N(seg)] = A[M,K] @ B[N,K]^T.  All operands pre-rounded to tf32 grid.
// CTA tile 128x128, BK=32, 2 stages, 8 warps 4x2 (warp 32x64), m16n8k8.
struct Seg {
    const float* A; const float* B; const float* bias;
    const float* p1; const float* p2; float* C;
    int N; int K; int epi; int rnd;
};

__global__ void __launch_bounds__(256,2) gemm_cp(Seg s0, Seg s1, Seg s2, Seg s3)
{
    extern __shared__ float sm[];
    Seg sg = (blockIdx.z==0)?s0:(blockIdx.z==1)?s1:(blockIdx.z==2)?s2:s3;
    const int tid = threadIdx.x, lane = tid & 31, wid = tid >> 5;
    const int bm = blockIdx.y*128, bn = blockIdx.x*128;
    const int wm = (wid & 3)*32, wn = (wid >> 2)*64;
    const int K = sg.K, N = sg.N;

    float acc[2][8][4];
    #pragma unroll
    for (int i=0;i<2;i++)
        #pragma unroll
        for (int j=0;j<8;j++)
            #pragma unroll
            for (int q=0;q<4;q++) acc[i][j][q]=0.f;

    // stage layout: stage*9216 floats; A[128][36], B[128][36]
    uint32_t smbase = (uint32_t)__cvta_generic_to_shared(sm);

    const int lrow = tid >> 1;            // unused helper removed
    (void)lrow;

    int nch = K >> 5;

    // loader: 4 A-vec4 + 4 B-vec4 per thread per chunk
    #define LOAD_CHUNK(c, st) { \
        int k0 = (c) << 5; \
        uint32_t ab = smbase + (uint32_t)(st)*9216u*4u; \
        uint32_t bb = ab + 4608u*4u; \
        _Pragma("unroll") \
        for (int i=0;i<4;i++){ \
            int v = i*256 + tid; \
            int row = v >> 3, c16 = v & 7; \
            const float* asrc = sg.A + (size_t)(bm+row)*K + k0 + c16*4; \
            uint32_t adst = ab + (uint32_t)(row*36 + c16*4)*4u; \
            asm volatile("cp.async.cg.shared.global [%0], [%1], 16;\n" :: "r"(adst), "l"(asrc)); \
            int n = bn + row; \
            const float* bsrc = sg.B + (size_t)n*K + k0 + c16*4; \
            uint32_t bdst = bb + (uint32_t)(row*36 + c16*4)*4u; \
            int szb = (n < N) ? 16 : 0; \
            asm volatile("cp.async.cg.shared.global [%0], [%1], 16, %2;\n" :: "r"(bdst), "l"(bsrc), "r"(szb)); \
        } \
        asm volatile("cp.async.commit_group;\n" ::: "memory"); }

    LOAD_CHUNK(0, 0);
    for (int c = 0; c < nch; c++) {
        int cur = c & 1;
        if (c + 1 < nch) {
            LOAD_CHUNK(c+1, (c+1)&1);
            asm volatile("cp.async.wait_group 1;\n" ::: "memory");
        } else {
            asm volatile("cp.async.wait_group 0;\n" ::: "memory");
        }
        __syncthreads();

        const float* As_ = sm + cur*9216;
        const float* Bs_ = As_ + 4608;
        #pragma unroll
        for (int s = 0; s < 4; s++) {
            int ks = (s << 3) + (lane & 3);
            uint32_t a[2][4];
            #pragma unroll
            for (int i = 0; i < 2; i++) {
                int r = wm + i*16 + (lane >> 2);
                a[i][0] = __float_as_uint(As_[r*36 + ks]);
                a[i][1] = __float_as_uint(As_[(r+8)*36 + ks]);
                a[i][2] = __float_as_uint(As_[r*36 + ks + 4]);
                a[i][3] = __float_as_uint(As_[(r+8)*36 + ks + 4]);
            }
            #pragma unroll
            for (int j = 0; j < 8; j++) {
                int n = wn + j*8 + (lane >> 2);
                uint32_t b0 = __float_as_uint(Bs_[n*36 + ks]);
                uint32_t b1 = __float_as_uint(Bs_[n*36 + ks + 4]);
                mma_tf32(acc[0][j], a[0], b0, b1);
                mma_tf32(acc[1][j], a[1], b0, b1);
            }
        }
        __syncthreads();
    }
    #undef LOAD_CHUNK

    // ---- epilogue ----
    int epi = sg.epi, rnd = sg.rnd;
    #pragma unroll
    for (int i = 0; i < 2; i++) {
        int r0 = bm + wm + i*16 + (lane >> 2);
        #pragma unroll
        for (int j = 0; j < 8; j++) {
            int col = bn + wn + j*8 + (lane & 3)*2;
            if (col >= N) continue;
            #pragma unroll
            for (int h = 0; h < 2; h++) {
                int m = r0 + h*8;
                size_t idx = (size_t)m*N + col;
                float v0 = acc[i][j][h*2+0];
                float v1 = acc[i][j][h*2+1];
                if (epi == EPI_TANH) { v0 = tanhf(v0); v1 = tanhf(v1); }
                else if (epi == EPI_SIG) { v0 = sigmoidf_(v0); v1 = sigmoidf_(v1); }
                else if (epi == EPI_SIGBIAS) {
                    v0 = sigmoidf_(v0 + sg.bias[col]); v1 = sigmoidf_(v1 + sg.bias[col+1]);
                } else if (epi == EPI_W) {
                    v0 = expf(-0.606531f * sigmoidf_(v0 + sg.bias[col]));
                    v1 = expf(-0.606531f * sigmoidf_(v1 + sg.bias[col+1]));
                } else if (epi == EPI_VMIX) {
                    float t0 = sigmoidf_(v0 + sg.bias[col]), t1 = sigmoidf_(v1 + sg.bias[col+1]);
                    float2 vr = *(const float2*)(sg.p1 + idx);
                    float2 vf = *(const float2*)(sg.p2 + idx);
                    v0 = vr.x + (vf.x - vr.x)*t0;
                    v1 = vr.y + (vf.y - vr.y)*t1;
                }
                if (rnd) { v0 = rnaf(v0); v1 = rnaf(v1); }
                *(float2*)(sg.C + idx) = make_float2(v0, v1);
            }
        }
    }
}

// ---------------- elementwise kernels ----------------
__device__ __forceinline__ float warp_red(float v) {
    #pragma unroll
    for (int s=16; s; s>>=1) v += __shfl_xor_sync(0xffffffffu, v, s);
    return v;
}

__global__ void prep_kernel(const float* __restrict__ kraw, const float* __restrict__ iclr,
                            const float* __restrict__ k_k, const float* __restrict__ k_a,
                            float* __restrict__ kk_out, float* __restrict__ kmod,
                            float* __restrict__ bout)
{
    int warp = threadIdx.x >> 5, lane = threadIdx.x & 31;
    int row = blockIdx.x*8 + warp;
    int m = row >> 4, h = row & 15;
    size_t off = (size_t)m*CD + h*CDh;
    int hh = h*CDh;

    float k1 = kraw[off+lane],     k2 = kraw[off+32+lane];
    float kk1 = k1*k_k[hh+lane],   kk2 = k2*k_k[hh+32+lane];
    float ss = warp_red(kk1*kk1 + kk2*kk2);
    float denom = fmaxf(sqrtf(ss), 1e-7f);
    kk1 /= denom; kk2 /= denom;
    kk_out[off+lane]    = kk1;
    kk_out[off+32+lane] = kk2;

    float i1 = iclr[off+lane], i2 = iclr[off+32+lane];
    kmod[off+lane]    = k1*(1.f + (i1-1.f)*k_a[hh+lane]);
    kmod[off+32+lane] = k2*(1.f + (i2-1.f)*k_a[hh+32+lane]);
    bout[off+lane]    = kk1*i1;
    bout[off+32+lane] = kk2*i2;
}

// WKV7 scan with 2-deep register prefetch.
__global__ void __launch_bounds__(128,1) scan_kernel(
    const float* __restrict__ r, const float* __restrict__ w,
    const float* __restrict__ k, const float* __restrict__ v,
    const float* __restrict__ kkv, const float* __restrict__ bv,
    float* __restrict__ y)
{
    int bh = blockIdx.x;
    int b = bh >> 4, h = bh & 15;
    int tid = threadIdx.x;
    int i = tid >> 1, half = tid & 1;
    int j0 = tid & 63, grp = tid >> 6;

    __shared__ float sh[2][6][64];
    float4 S[8];
    #pragma unroll
    for (int q=0;q<8;q++) S[q] = make_float4(0.f,0.f,0.f,0.f);

    size_t base = (size_t)b*CL*CD + (size_t)h*CDh;

    float pf[2][3];
    {
        size_t o0 = base + j0, o1 = base + CD + j0;
        if (grp == 0) {
            pf[0][0]=r[o0]; pf[0][1]=w[o0]; pf[0][2]=k[o0];
            pf[1][0]=r[o1]; pf[1][1]=w[o1]; pf[1][2]=k[o1];
        } else {
            pf[0][0]=v[o0]; pf[0][1]=kkv[o0]; pf[0][2]=bv[o0];
            pf[1][0]=v[o1]; pf[1][1]=kkv[o1]; pf[1][2]=bv[o1];
        }
    }

    for (int t=0; t<CL; t++) {
        int s = t & 1;
        if (grp == 0) {
            sh[s][0][j0]=pf[s][0]; sh[s][1][j0]=pf[s][1]; sh[s][2][j0]=pf[s][2];
        } else {
            sh[s][3][j0]=pf[s][0]; sh[s][4][j0]=pf[s][1]; sh[s][5][j0]=pf[s][2];
        }
        __syncthreads();
        if (t + 2 < CL) {
            size_t o = base + (size_t)(t+2)*CD + j0;
            if (grp == 0) { pf[s][0]=r[o]; pf[s][1]=w[o]; pf[s][2]=k[o]; }
            else          { pf[s][0]=v[o]; pf[s][1]=kkv[o]; pf[s][2]=bv[o]; }
        }

        const float4* r4 = (const float4*)&sh[s][0][half*32];
        const float4* w4 = (const float4*)&sh[s][1][half*32];
        const float4* k4 = (const float4*)&sh[s][2][half*32];
        const float4* a4 = (const float4*)&sh[s][4][half*32];
        const float4* b4 = (const float4*)&sh[s][5][half*32];
        float vi = sh[s][3][i];

        float dot = 0.f;
        #pragma unroll
        for (int q=0;q<8;q++) {
            float4 aq = a4[q];
            dot += S[q].x*aq.x + S[q].y*aq.y + S[q].z*aq.z + S[q].w*aq.w;
        }
        dot += __shfl_xor_sync(0xffffffffu, dot, 1);
        float sa = -dot;

        float yl = 0.f;
        #pragma unroll
        for (int q=0;q<8;q++) {
            float4 wq=w4[q], kq=k4[q], bq=b4[q], rq=r4[q];
            S[q].x = S[q].x*wq.x + vi*kq.x + sa*bq.x; yl += S[q].x*rq.x;
            S[q].y = S[q].y*wq.y + vi*kq.y + sa*bq.y; yl += S[q].y*rq.y;
            S[q].z = S[q].z*wq.z + vi*kq.z + sa*bq.z; yl += S[q].z*rq.z;
            S[q].w = S[q].w*wq.w + vi*kq.w + sa*bq.w; yl += S[q].w*rq.w;
        }
        yl += __shfl_xor_sync(0xffffffffu, yl, 1);
        if (half == 0) y[base + (size_t)t*CD + i] = yl;
    }
}

__global__ void post_kernel(const float* __restrict__ y, const float* __restrict__ r,
                            const float* __restrict__ kmod, const float* __restrict__ vmix,
                            const float* __restrict__ gate, const float* __restrict__ gnw,
                            const float* __restrict__ gnb, const float* __restrict__ r_k,
                            float* __restrict__ pre)
{
    int warp = threadIdx.x >> 5, lane = threadIdx.x & 31;
    int row = blockIdx.x*8 + warp;
    int m = row >> 4, h = row & 15;
    size_t off = (size_t)m*CD + h*CDh;
    int hh = h*CDh;

    float y1 = y[off+lane], y2 = y[off+32+lane];
    float mean = warp_red(y1 + y2) * (1.f/64.f);
    float d1 = y1 - mean, d2 = y2 - mean;
    float var = warp_red(d1*d1 + d2*d2) * (1.f/64.f);
    float inv = 1.f / sqrtf(var + 0.00064f);
    float o1 = gnw[hh+lane]   *d1*inv + gnb[hh+lane];
    float o2 = gnw[hh+32+lane]*d2*inv + gnb[hh+32+lane];

    float bonus = warp_red(r[off+lane]*kmod[off+lane]*r_k[hh+lane]
                         + r[off+32+lane]*kmod[off+32+lane]*r_k[hh+32+lane]);
    o1 += bonus * vmix[off+lane];
    o2 += bonus * vmix[off+32+lane];
    // tf32-round: pre feeds the Wo GEMM via cp.async
    pre[off+lane]    = rnaf(o1 * gate[off+lane]);
    pre[off+32+lane] = rnaf(o2 * gate[off+32+lane]);
}

// ---------------- host ----------------
extern "C" void kernel_launch(void* const* d_in, const int* in_sizes, int n_in,
                              void* d_out, int out_size)
{
    const float* x      = (const float*)d_in[0];
    const float* vfirst = (const float*)d_in[1];
    const float* x_r    = (const float*)d_in[2];
    const float* x_w    = (const float*)d_in[3];
    const float* x_k    = (const float*)d_in[4];
    const float* x_v    = (const float*)d_in[5];
    const float* x_a    = (const float*)d_in[6];
    const float* x_g    = (const float*)d_in[7];
    const float* k_k    = (const float*)d_in[8];
    const float* k_a    = (const float*)d_in[9];
    const float* r_k    = (const float*)d_in[10];
    const float* Wr     = (const float*)d_in[11];
    const float* Wk     = (const float*)d_in[12];
    const float* Wv     = (const float*)d_in[13];
    const float* Wo     = (const float*)d_in[14];
    const float* gnw    = (const float*)d_in[15];
    const float* gnb    = (const float*)d_in[16];
    const float* wA     = (const float*)d_in[17];
    const float* wB     = (const float*)d_in[18];
    const float* wb     = (const float*)d_in[19];
    const float* vA     = (const float*)d_in[20];
    const float* vB     = (const float*)d_in[21];
    const float* vb     = (const float*)d_in[22];
    const float* aA     = (const float*)d_in[23];
    const float* aB     = (const float*)d_in[24];
    const float* ab     = (const float*)d_in[25];
    const float* gA     = (const float*)d_in[26];
    const float* gB     = (const float*)d_in[27];
    float* out = (float*)d_out;

    float* S;
    cudaGetSymbolAddress((void**)&S, g_scratch);
    float* p_xr   = S + 0ull*MDSZ;
    float* p_xw   = S + 1ull*MDSZ;
    float* p_xk   = S + 2ull*MDSZ;
    float* p_xv   = S + 3ull*MDSZ;
    float* p_xa   = S + 4ull*MDSZ;
    float* p_xg   = S + 5ull*MDSZ;
    float* g_r    = S + 6ull*MDSZ;
    float* g_kraw = S + 7ull*MDSZ;
    float* g_vraw = S + 8ull*MDSZ;
    float* g_w    = S + 9ull*MDSZ;
    float* g_iclr = S + 10ull*MDSZ;
    float* g_vmix = S + 11ull*MDSZ;
    float* g_gate = S + 12ull*MDSZ;
    float* g_kk   = S + 13ull*MDSZ;
    float* g_km   = S + 14ull*MDSZ;
    float* g_b    = S + 15ull*MDSZ;
    float* g_y    = S + 16ull*MDSZ;
    float* g_pre  = S + 17ull*MDSZ;
    float* WBUF   = S + 18ull*MDSZ;
    float* HBUF   = S + 19ull*MDSZ;

    // rounded weight layout
    float* rWr = WBUF + 0;
    float* rWk = WBUF + 1048576;
    float* rWv = WBUF + 2097152;
    float* rWo = WBUF + 3145728;
    float* rwA = WBUF + 4194304;
    float* raA = WBUF + 4259840;
    float* rvA = WBUF + 4325376;
    float* rgA = WBUF + 4358144;
    float* rwB = WBUF + 4489216;
    float* raB = WBUF + 4554752;
    float* rvB = WBUF + 4620288;
    float* rgB = WBUF + 4653056;

    // lora hidden planes
    float* h_w = HBUF + 0;        // [M,64]
    float* h_a = HBUF + 524288;   // [M,64]
    float* h_v = HBUF + 1048576;  // [M,32]
    float* h_g = HBUF + 1310720;  // [M,128]

    const int SMEM = 2*9216*4;  // 73728 bytes
    cudaFuncSetAttribute(gemm_cp, cudaFuncAttributeMaxDynamicSharedMemorySize, SMEM);

    // 1) token-shift mix + tf32 rounding (6 planes)
    mix6_kernel<<<CM*CD/4/256, 256>>>(x, x_r, x_w, x_k, x_v, x_a, x_g,
                                      p_xr, p_xw, p_xk, p_xv, p_xa, p_xg);

    // 2) round weights
    {
        RW12 rw;
        const float* srcs[12] = {Wr,Wk,Wv,Wo, wA,aA,vA,gA, wB,aB,vB,gB};
        float* dsts[12] = {rWr,rWk,rWv,rWo, rwA,raA,rvA,rgA, rwB,raB,rvB,rgB};
        int ns[12] = {1048576,1048576,1048576,1048576, 65536,65536,32768,131072,
                      65536,65536,32768,131072};
        for (int i=0;i<12;i++){ rw.s[i]=srcs[i]; rw.d[i]=dsts[i]; rw.n[i]=ns[i]; }
        roundw_kernel<<<dim3(256,12), 256>>>(rw);
    }

    Seg z; z.A=nullptr; z.B=nullptr; z.bias=nullptr; z.p1=nullptr; z.p2=nullptr;
    z.C=nullptr; z.N=0; z.K=0; z.epi=EPI_NONE; z.rnd=0;

    // 3) big r/k/v projections, fused z=3
    {
        Seg sr=z, sk=z, sv=z;
        sr.A=p_xr; sr.B=rWr; sr.C=g_r;    sr.N=CD; sr.K=CD;
        sk.A=p_xk; sk.B=rWk; sk.C=g_kraw; sk.N=CD; sk.K=CD;
        sv.A=p_xv; sv.B=rWv; sv.C=g_vraw; sv.N=CD; sv.K=CD;
        gemm_cp<<<dim3(CD/128, CM/128, 3), 256, SMEM>>>(sr, sk, sv, sv);
    }

    // 4) LoRA stage-1, fused z=4 (outputs tf32-rounded for stage-2 cp.async)
    {
        Seg sw=z, sa=z, sv=z, sg=z;
        sw.A=p_xw; sw.B=rwA; sw.C=h_w; sw.N=64;  sw.K=CD; sw.epi=EPI_TANH; sw.rnd=1;
        sa.A=p_xa; sa.B=raA; sa.C=h_a; sa.N=64;  sa.K=CD; sa.epi=EPI_NONE; sa.rnd=1;
        sv.A=p_xv; sv.B=rvA; sv.C=h_v; sv.N=32;  sv.K=CD; sv.epi=EPI_NONE; sv.rnd=1;
        sg.A=p_xg; sg.B=rgA; sg.C=h_g; sg.N=128; sg.K=CD; sg.epi=EPI_SIG;  sg.rnd=1;
        gemm_cp<<<dim3(1, CM/128, 4), 256, SMEM>>>(sw, sa, sv, sg);
    }

    // 5) LoRA stage-2, fused z=4
    {
        Seg sw=z, sa=z, sv=z, sg=z;
        sw.A=h_w; sw.B=rwB; sw.bias=wb; sw.C=g_w;    sw.N=CD; sw.K=64;  sw.epi=EPI_W;
        sa.A=h_a; sa.B=raB; sa.bias=ab; sa.C=g_iclr; sa.N=CD; sa.K=64;  sa.epi=EPI_SIGBIAS;
        sv.A=h_v; sv.B=rvB; sv.bias=vb; sv.C=g_vmix; sv.N=CD; sv.K=32;  sv.epi=EPI_VMIX;
        sv.p1=g_vraw; sv.p2=vfirst;
        sg.A=h_g; sg.B=rgB; sg.C=g_gate; sg.N=CD; sg.K=128; sg.epi=EPI_NONE;
        gemm_cp<<<dim3(CD/128, CM/128, 4), 256, SMEM>>>(sw, sa, sv, sg);
    }

    // 6) kk normalize / k modify / b
    prep_kernel<<<CM*CH/8, 256>>>(g_kraw, g_iclr, k_k, k_a, g_kk, g_km, g_b);

    // 7) sequential WKV7 scan
    scan_kernel<<<CB*CH, 128>>>(g_r, g_w, g_km, g_vmix, g_kk, g_b, g_y);

    // 8) groupnorm + bonus + gate (writes rounded pre)
    post_kernel<<<CM*CH/8, 256>>>(g_y, g_r, g_km, g_vmix, g_gate, gnw, gnb, r_k, g_pre);

    // 9) output projection
    {
        Seg so=z;
        so.A=g_pre; so.B=rWo; so.C=out; so.N=CD; so.K=CD;
        gemm_cp<<<dim3(CD/128, CM/128, 1), 256, SMEM>>>(so, so, so, so);
    }
}

// round 5
// speedup vs baseline: 1.8041x; 1.0365x over previous
#include <cuda_runtime.h>
#include <cuda_bf16.h>
#include <math.h>
#include <stdint.h>

// Problem constants
#define CB 4
#define CL 2048
#define CD 1024
#define CH 16
#define CDh 64
#define CM (CB*CL)          // 8192 rows
#define MDSZ (8388608)      // CM*CD elements per scratch plane

__device__ float g_scratch[20ull*MDSZ];

enum { EPI_NONE=0, EPI_TANH=1, EPI_SIG=2, EPI_SIGBIAS=3, EPI_W=4, EPI_VMIX=5 };

__device__ __forceinline__ float sigmoidf_(float x){ return 1.f/(1.f+expf(-x)); }

__device__ __forceinline__ uint32_t to_tf32(float f){
    uint32_t u; asm("cvt.rna.tf32.f32 %0, %1;" : "=r"(u) : "f"(f)); return u;
}
__device__ __forceinline__ float rnaf(float f){ return __uint_as_float(to_tf32(f)); }

__device__ __forceinline__ void mma_tf32(float* c, const uint32_t* a, uint32_t b0, uint32_t b1){
    asm volatile(
        "mma.sync.aligned.m16n8k8.row.col.f32.tf32.tf32.f32 "
        "{%0,%1,%2,%3}, {%4,%5,%6,%7}, {%8,%9}, {%0,%1,%2,%3};"
        : "+f"(c[0]), "+f"(c[1]), "+f"(c[2]), "+f"(c[3])
        : "r"(a[0]), "r"(a[1]), "r"(a[2]), "r"(a[3]), "r"(b0), "r"(b1));
}

// ---------------- mix + tf32-round: 6 planes from x ----------------
__global__ void __launch_bounds__(256) mix6_kernel(
    const float* __restrict__ x,
    const float* __restrict__ m0, const float* __restrict__ m1,
    const float* __restrict__ m2, const float* __restrict__ m3,
    const float* __restrict__ m4, const float* __restrict__ m5,
    float* __restrict__ o0, float* __restrict__ o1, float* __restrict__ o2,
    float* __restrict__ o3, float* __restrict__ o4, float* __restrict__ o5)
{
    size_t v = (size_t)blockIdx.x*256 + threadIdx.x;
    int m = (int)(v >> 8);
    int kp = (int)(v & 255) << 2;
    size_t off = (size_t)m*CD + kp;
    float4 xv = *(const float4*)(x + off);
    float4 xp = make_float4(0.f,0.f,0.f,0.f);
    if (m % CL) xp = *(const float4*)(x + off - CD);
    float4 dx = make_float4(xp.x-xv.x, xp.y-xv.y, xp.z-xv.z, xp.w-xv.w);

    #define DO_MIX(MI, OI) { \
        float4 mx = *(const float4*)(MI + kp); \
        float4 r; \
        r.x = rnaf(fmaf(dx.x, mx.x, xv.x)); \
        r.y = rnaf(fmaf(dx.y, mx.y, xv.y)); \
        r.z = rnaf(fmaf(dx.z, mx.z, xv.z)); \
        r.w = rnaf(fmaf(dx.w, mx.w, xv.w)); \
        *(float4*)(OI + off) = r; }
    DO_MIX(m0, o0); DO_MIX(m1, o1); DO_MIX(m2, o2);
    DO_MIX(m3, o3); DO_MIX(m4, o4); DO_MIX(m5, o5);
    #undef DO_MIX
}

// ---------------- round 12 weight buffers ----------------
struct RW12 { const float* s[12]; float* d[12]; int n[12]; };
__global__ void __launch_bounds__(256) roundw_kernel(RW12 w)
{
    int seg = blockIdx.y;
    int n4 = w.n[seg] >> 2;
    const float* s = w.s[seg];
    float* d = w.d[seg];
    for (int v = blockIdx.x*256 + threadIdx.x; v < n4; v += gridDim.x*256) {
        float4 a = *(const float4*)(s + v*4);
        float4 r = make_float4(rnaf(a.x), rnaf(a.y), rnaf(a.z), rnaf(a.w));
        *(float4*)(d + v*4) = r;
    }
}

// ---------------- cp.async double-buffered tf32 GEMM ----------------
struct Seg {
    const float* A; const float* B; const float* bias;
    const float* p1; const float* p2; float* C;
    int N; int K; int epi; int rnd;
};

__global__ void __launch_bounds__(256,2) gemm_cp(Seg s0, Seg s1, Seg s2, Seg s3)
{
    extern __shared__ float sm[];
    Seg sg = (blockIdx.z==0)?s0:(blockIdx.z==1)?s1:(blockIdx.z==2)?s2:s3;
    const int tid = threadIdx.x, lane = tid & 31, wid = tid >> 5;
    const int bm = blockIdx.y*128, bn = blockIdx.x*128;
    const int wm = (wid & 3)*32, wn = (wid >> 2)*64;
    const int K = sg.K, N = sg.N;

    float acc[2][8][4];
    #pragma unroll
    for (int i=0;i<2;i++)
        #pragma unroll
        for (int j=0;j<8;j++)
            #pragma unroll
            for (int q=0;q<4;q++) acc[i][j][q]=0.f;

    uint32_t smbase = (uint32_t)__cvta_generic_to_shared(sm);
    int nch = K >> 5;

    #define LOAD_CHUNK(c, st) { \
        int k0 = (c) << 5; \
        uint32_t ab = smbase + (uint32_t)(st)*9216u*4u; \
        uint32_t bb = ab + 4608u*4u; \
        _Pragma("unroll") \
        for (int i=0;i<4;i++){ \
            int v = i*256 + tid; \
            int row = v >> 3, c16 = v & 7; \
            const float* asrc = sg.A + (size_t)(bm+row)*K + k0 + c16*4; \
            uint32_t adst = ab + (uint32_t)(row*36 + c16*4)*4u; \
            asm volatile("cp.async.cg.shared.global [%0], [%1], 16;\n" :: "r"(adst), "l"(asrc)); \
            int n = bn + row; \
            const float* bsrc = sg.B + (size_t)n*K + k0 + c16*4; \
            uint32_t bdst = bb + (uint32_t)(row*36 + c16*4)*4u; \
            int szb = (n < N) ? 16 : 0; \
            asm volatile("cp.async.cg.shared.global [%0], [%1], 16, %2;\n" :: "r"(bdst), "l"(bsrc), "r"(szb)); \
        } \
        asm volatile("cp.async.commit_group;\n" ::: "memory"); }

    LOAD_CHUNK(0, 0);
    for (int c = 0; c < nch; c++) {
        int cur = c & 1;
        if (c + 1 < nch) {
            LOAD_CHUNK(c+1, (c+1)&1);
            asm volatile("cp.async.wait_group 1;\n" ::: "memory");
        } else {
            asm volatile("cp.async.wait_group 0;\n" ::: "memory");
        }
        __syncthreads();

        const float* As_ = sm + cur*9216;
        const float* Bs_ = As_ + 4608;
        #pragma unroll
        for (int s = 0; s < 4; s++) {
            int ks = (s << 3) + (lane & 3);
            uint32_t a[2][4];
            #pragma unroll
            for (int i = 0; i < 2; i++) {
                int r = wm + i*16 + (lane >> 2);
                a[i][0] = __float_as_uint(As_[r*36 + ks]);
                a[i][1] = __float_as_uint(As_[(r+8)*36 + ks]);
                a[i][2] = __float_as_uint(As_[r*36 + ks + 4]);
                a[i][3] = __float_as_uint(As_[(r+8)*36 + ks + 4]);
            }
            #pragma unroll
            for (int j = 0; j < 8; j++) {
                int n = wn + j*8 + (lane >> 2);
                uint32_t b0 = __float_as_uint(Bs_[n*36 + ks]);
                uint32_t b1 = __float_as_uint(Bs_[n*36 + ks + 4]);
                mma_tf32(acc[0][j], a[0], b0, b1);
                mma_tf32(acc[1][j], a[1], b0, b1);
            }
        }
        __syncthreads();
    }
    #undef LOAD_CHUNK

    int epi = sg.epi, rnd = sg.rnd;
    #pragma unroll
    for (int i = 0; i < 2; i++) {
        int r0 = bm + wm + i*16 + (lane >> 2);
        #pragma unroll
        for (int j = 0; j < 8; j++) {
            int col = bn + wn + j*8 + (lane & 3)*2;
            if (col >= N) continue;
            #pragma unroll
            for (int h = 0; h < 2; h++) {
                int m = r0 + h*8;
                size_t idx = (size_t)m*N + col;
                float v0 = acc[i][j][h*2+0];
                float v1 = acc[i][j][h*2+1];
                if (epi == EPI_TANH) { v0 = tanhf(v0); v1 = tanhf(v1); }
                else if (epi == EPI_SIG) { v0 = sigmoidf_(v0); v1 = sigmoidf_(v1); }
                else if (epi == EPI_SIGBIAS) {
                    v0 = sigmoidf_(v0 + sg.bias[col]); v1 = sigmoidf_(v1 + sg.bias[col+1]);
                } else if (epi == EPI_W) {
                    v0 = expf(-0.606531f * sigmoidf_(v0 + sg.bias[col]));
                    v1 = expf(-0.606531f * sigmoidf_(v1 + sg.bias[col+1]));
                } else if (epi == EPI_VMIX) {
                    float t0 = sigmoidf_(v0 + sg.bias[col]), t1 = sigmoidf_(v1 + sg.bias[col+1]);
                    float2 vr = *(const float2*)(sg.p1 + idx);
                    float2 vf = *(const float2*)(sg.p2 + idx);
                    v0 = vr.x + (vf.x - vr.x)*t0;
                    v1 = vr.y + (vf.y - vr.y)*t1;
                }
                if (rnd) { v0 = rnaf(v0); v1 = rnaf(v1); }
                *(float2*)(sg.C + idx) = make_float2(v0, v1);
            }
        }
    }
}

// ---------------- elementwise kernels ----------------
__device__ __forceinline__ float warp_red(float v) {
    #pragma unroll
    for (int s=16; s; s>>=1) v += __shfl_xor_sync(0xffffffffu, v, s);
    return v;
}

__global__ void prep_kernel(const float* __restrict__ kraw, const float* __restrict__ iclr,
                            const float* __restrict__ k_k, const float* __restrict__ k_a,
                            float* __restrict__ kk_out, float* __restrict__ kmod,
                            float* __restrict__ bout)
{
    int warp = threadIdx.x >> 5, lane = threadIdx.x & 31;
    int row = blockIdx.x*8 + warp;
    int m = row >> 4, h = row & 15;
    size_t off = (size_t)m*CD + h*CDh;
    int hh = h*CDh;

    float k1 = kraw[off+lane],     k2 = kraw[off+32+lane];
    float kk1 = k1*k_k[hh+lane],   kk2 = k2*k_k[hh+32+lane];
    float ss = warp_red(kk1*kk1 + kk2*kk2);
    float denom = fmaxf(sqrtf(ss), 1e-7f);
    kk1 /= denom; kk2 /= denom;
    kk_out[off+lane]    = kk1;
    kk_out[off+32+lane] = kk2;

    float i1 = iclr[off+lane], i2 = iclr[off+32+lane];
    kmod[off+lane]    = k1*(1.f + (i1-1.f)*k_a[hh+lane]);
    kmod[off+32+lane] = k2*(1.f + (i2-1.f)*k_a[hh+32+lane]);
    bout[off+lane]    = kk1*i1;
    bout[off+32+lane] = kk2*i2;
}

// ---------------- WKV7 scan: warp-uniform column halves ----------------
// 128 threads, 4 warps. Warps 0-1: columns 0-31; warps 2-3: columns 32-63.
// lane+32*(wid&1) = state row. All vector LDS are same-address broadcasts.
__global__ void __launch_bounds__(128,1) scan_kernel(
    const float* __restrict__ r, const float* __restrict__ w,
    const float* __restrict__ k, const float* __restrict__ v,
    const float* __restrict__ kkv, const float* __restrict__ bv,
    float* __restrict__ y)
{
    int bh = blockIdx.x;
    int b = bh >> 4, h = bh & 15;
    int tid = threadIdx.x;
    int lane = tid & 31, wid = tid >> 5;
    int half = wid >> 1;                 // column half owned by this warp
    int row = ((wid & 1) << 5) + lane;   // state row 0..63
    int cb = half << 5;                  // column base
    int j0 = tid & 63, grp = tid >> 6;   // staging role

    __shared__ float sh[2][6][64];       // 0=r 1=w 2=k 3=v 4=kk(a) 5=b
    __shared__ float dotbuf[2][64];      // per-half sa partials
    __shared__ float ybuf[2][64];        // half1 y partials, double buffered

    float4 S[8];
    #pragma unroll
    for (int q=0;q<8;q++) S[q] = make_float4(0.f,0.f,0.f,0.f);

    size_t base = (size_t)b*CL*CD + (size_t)h*CDh;

    float pf[2][3];
    {
        size_t o0 = base + j0, o1 = base + CD + j0;
        if (grp == 0) {
            pf[0][0]=r[o0]; pf[0][1]=w[o0]; pf[0][2]=k[o0];
            pf[1][0]=r[o1]; pf[1][1]=w[o1]; pf[1][2]=k[o1];
        } else {
            pf[0][0]=v[o0]; pf[0][1]=kkv[o0]; pf[0][2]=bv[o0];
            pf[1][0]=v[o1]; pf[1][1]=kkv[o1]; pf[1][2]=bv[o1];
        }
    }

    float ypPrev = 0.f;

    for (int t=0; t<CL; t++) {
        int s = t & 1;
        // stage inputs for step t
        if (grp == 0) {
            sh[s][0][j0]=pf[s][0]; sh[s][1][j0]=pf[s][1]; sh[s][2][j0]=pf[s][2];
        } else {
            sh[s][3][j0]=pf[s][0]; sh[s][4][j0]=pf[s][1]; sh[s][5][j0]=pf[s][2];
        }
        __syncthreads();   // barrier 1: sh[t] visible; also orders ybuf writes of t-1

        // complete y of step t-1 (half 0 combines with half 1's partial)
        if (half == 0 && t > 0) {
            y[base + (size_t)(t-1)*CD + row] = ypPrev + ybuf[s^1][row];
        }
        // prefetch t+2
        if (t + 2 < CL) {
            size_t o = base + (size_t)(t+2)*CD + j0;
            if (grp == 0) { pf[s][0]=r[o]; pf[s][1]=w[o]; pf[s][2]=k[o]; }
            else          { pf[s][0]=v[o]; pf[s][1]=kkv[o]; pf[s][2]=bv[o]; }
        }

        // phase A: dot partial over this warp's column half (broadcast LDS)
        {
            float d0=0.f,d1=0.f,d2=0.f,d3=0.f;
            #pragma unroll
            for (int q=0;q<8;q++) {
                float4 aq = *(const float4*)&sh[s][4][cb + (q<<2)];
                d0 += S[q].x*aq.x; d1 += S[q].y*aq.y;
                d2 += S[q].z*aq.z; d3 += S[q].w*aq.w;
            }
            dotbuf[half][row] = (d0+d1)+(d2+d3);
        }
        __syncthreads();   // barrier 2: dot partials visible

        {
            float sa = -(dotbuf[0][row] + dotbuf[1][row]);
            float vi = sh[s][3][row];
            float y0=0.f,y1=0.f,y2=0.f,y3=0.f;
            #pragma unroll
            for (int q=0;q<8;q++) {
                int c4 = cb + (q<<2);
                float4 wq = *(const float4*)&sh[s][1][c4];
                float4 kq = *(const float4*)&sh[s][2][c4];
                float4 bq = *(const float4*)&sh[s][5][c4];
                float4 rq = *(const float4*)&sh[s][0][c4];
                S[q].x = S[q].x*wq.x + vi*kq.x + sa*bq.x; y0 += S[q].x*rq.x;
                S[q].y = S[q].y*wq.y + vi*kq.y + sa*bq.y; y1 += S[q].y*rq.y;
                S[q].z = S[q].z*wq.z + vi*kq.z + sa*bq.z; y2 += S[q].z*rq.z;
                S[q].w = S[q].w*wq.w + vi*kq.w + sa*bq.w; y3 += S[q].w*rq.w;
            }
            float yp = (y0+y1)+(y2+y3);
            if (half == 1) ybuf[s][row] = yp;
            else           ypPrev = yp;
        }
        // no barrier here: next iteration's barrier 1 orders ybuf/dotbuf reuse
    }

    __syncthreads();
    if (half == 0) {
        y[base + (size_t)(CL-1)*CD + row] = ypPrev + ybuf[(CL-1)&1][row];
    }
}

__global__ void post_kernel(const float* __restrict__ y, const float* __restrict__ r,
                            const float* __restrict__ kmod, const float* __restrict__ vmix,
                            const float* __restrict__ gate, const float* __restrict__ gnw,
                            const float* __restrict__ gnb, const float* __restrict__ r_k,
                            float* __restrict__ pre)
{
    int warp = threadIdx.x >> 5, lane = threadIdx.x & 31;
    int row = blockIdx.x*8 + warp;
    int m = row >> 4, h = row & 15;
    size_t off = (size_t)m*CD + h*CDh;
    int hh = h*CDh;

    float y1 = y[off+lane], y2 = y[off+32+lane];
    float mean = warp_red(y1 + y2) * (1.f/64.f);
    float d1 = y1 - mean, d2 = y2 - mean;
    float var = warp_red(d1*d1 + d2*d2) * (1.f/64.f);
    float inv = 1.f / sqrtf(var + 0.00064f);
    float o1 = gnw[hh+lane]   *d1*inv + gnb[hh+lane];
    float o2 = gnw[hh+32+lane]*d2*inv + gnb[hh+32+lane];

    float bonus = warp_red(r[off+lane]*kmod[off+lane]*r_k[hh+lane]
                         + r[off+32+lane]*kmod[off+32+lane]*r_k[hh+32+lane]);
    o1 += bonus * vmix[off+lane];
    o2 += bonus * vmix[off+32+lane];
    pre[off+lane]    = rnaf(o1 * gate[off+lane]);
    pre[off+32+lane] = rnaf(o2 * gate[off+32+lane]);
}

// ---------------- host ----------------
extern "C" void kernel_launch(void* const* d_in, const int* in_sizes, int n_in,
                              void* d_out, int out_size)
{
    const float* x      = (const float*)d_in[0];
    const float* vfirst = (const float*)d_in[1];
    const float* x_r    = (const float*)d_in[2];
    const float* x_w    = (const float*)d_in[3];
    const float* x_k    = (const float*)d_in[4];
    const float* x_v    = (const float*)d_in[5];
    const float* x_a    = (const float*)d_in[6];
    const float* x_g    = (const float*)d_in[7];
    const float* k_k    = (const float*)d_in[8];
    const float* k_a    = (const float*)d_in[9];
    const float* r_k    = (const float*)d_in[10];
    const float* Wr     = (const float*)d_in[11];
    const float* Wk     = (const float*)d_in[12];
    const float* Wv     = (const float*)d_in[13];
    const float* Wo     = (const float*)d_in[14];
    const float* gnw    = (const float*)d_in[15];
    const float* gnb    = (const float*)d_in[16];
    const float* wA     = (const float*)d_in[17];
    const float* wB     = (const float*)d_in[18];
    const float* wb     = (const float*)d_in[19];
    const float* vA     = (const float*)d_in[20];
    const float* vB     = (const float*)d_in[21];
    const float* vb     = (const float*)d_in[22];
    const float* aA     = (const float*)d_in[23];
    const float* aB     = (const float*)d_in[24];
    const float* ab     = (const float*)d_in[25];
    const float* gA     = (const float*)d_in[26];
    const float* gB     = (const float*)d_in[27];
    float* out = (float*)d_out;

    float* S;
    cudaGetSymbolAddress((void**)&S, g_scratch);
    float* p_xr   = S + 0ull*MDSZ;
    float* p_xw   = S + 1ull*MDSZ;
    float* p_xk   = S + 2ull*MDSZ;
    float* p_xv   = S + 3ull*MDSZ;
    float* p_xa   = S + 4ull*MDSZ;
    float* p_xg   = S + 5ull*MDSZ;
    float* g_r    = S + 6ull*MDSZ;
    float* g_kraw = S + 7ull*MDSZ;
    float* g_vraw = S + 8ull*MDSZ;
    float* g_w    = S + 9ull*MDSZ;
    float* g_iclr = S + 10ull*MDSZ;
    float* g_vmix = S + 11ull*MDSZ;
    float* g_gate = S + 12ull*MDSZ;
    float* g_kk   = S + 13ull*MDSZ;
    float* g_km   = S + 14ull*MDSZ;
    float* g_b    = S + 15ull*MDSZ;
    float* g_y    = S + 16ull*MDSZ;
    float* g_pre  = S + 17ull*MDSZ;
    float* WBUF   = S + 18ull*MDSZ;
    float* HBUF   = S + 19ull*MDSZ;

    float* rWr = WBUF + 0;
    float* rWk = WBUF + 1048576;
    float* rWv = WBUF + 2097152;
    float* rWo = WBUF + 3145728;
    float* rwA = WBUF + 4194304;
    float* raA = WBUF + 4259840;
    float* rvA = WBUF + 4325376;
    float* rgA = WBUF + 4358144;
    float* rwB = WBUF + 4489216;
    float* raB = WBUF + 4554752;
    float* rvB = WBUF + 4620288;
    float* rgB = WBUF + 4653056;

    float* h_w = HBUF + 0;
    float* h_a = HBUF + 524288;
    float* h_v = HBUF + 1048576;
    float* h_g = HBUF + 1310720;

    const int SMEM = 2*9216*4;
    cudaFuncSetAttribute(gemm_cp, cudaFuncAttributeMaxDynamicSharedMemorySize, SMEM);

    mix6_kernel<<<CM*CD/4/256, 256>>>(x, x_r, x_w, x_k, x_v, x_a, x_g,
                                      p_xr, p_xw, p_xk, p_xv, p_xa, p_xg);

    {
        RW12 rw;
        const float* srcs[12] = {Wr,Wk,Wv,Wo, wA,aA,vA,gA, wB,aB,vB,gB};
        float* dsts[12] = {rWr,rWk,rWv,rWo, rwA,raA,rvA,rgA, rwB,raB,rvB,rgB};
        int ns[12] = {1048576,1048576,1048576,1048576, 65536,65536,32768,131072,
                      65536,65536,32768,131072};
        for (int i=0;i<12;i++){ rw.s[i]=srcs[i]; rw.d[i]=dsts[i]; rw.n[i]=ns[i]; }
        roundw_kernel<<<dim3(256,12), 256>>>(rw);
    }

    Seg z; z.A=nullptr; z.B=nullptr; z.bias=nullptr; z.p1=nullptr; z.p2=nullptr;
    z.C=nullptr; z.N=0; z.K=0; z.epi=EPI_NONE; z.rnd=0;

    {
        Seg sr=z, sk=z, sv=z;
        sr.A=p_xr; sr.B=rWr; sr.C=g_r;    sr.N=CD; sr.K=CD;
        sk.A=p_xk; sk.B=rWk; sk.C=g_kraw; sk.N=CD; sk.K=CD;
        sv.A=p_xv; sv.B=rWv; sv.C=g_vraw; sv.N=CD; sv.K=CD;
        gemm_cp<<<dim3(CD/128, CM/128, 3), 256, SMEM>>>(sr, sk, sv, sv);
    }

    {
        Seg sw=z, sa=z, sv=z, sg=z;
        sw.A=p_xw; sw.B=rwA; sw.C=h_w; sw.N=64;  sw.K=CD; sw.epi=EPI_TANH; sw.rnd=1;
        sa.A=p_xa; sa.B=raA; sa.C=h_a; sa.N=64;  sa.K=CD; sa.epi=EPI_NONE; sa.rnd=1;
        sv.A=p_xv; sv.B=rvA; sv.C=h_v; sv.N=32;  sv.K=CD; sv.epi=EPI_NONE; sv.rnd=1;
        sg.A=p_xg; sg.B=rgA; sg.C=h_g; sg.N=128; sg.K=CD; sg.epi=EPI_SIG;  sg.rnd=1;
        gemm_cp<<<dim3(1, CM/128, 4), 256, SMEM>>>(sw, sa, sv, sg);
    }

    {
        Seg sw=z, sa=z, sv=z, sg=z;
        sw.A=h_w; sw.B=rwB; sw.bias=wb; sw.C=g_w;    sw.N=CD; sw.K=64;  sw.epi=EPI_W;
        sa.A=h_a; sa.B=raB; sa.bias=ab; sa.C=g_iclr; sa.N=CD; sa.K=64;  sa.epi=EPI_SIGBIAS;
        sv.A=h_v; sv.B=rvB; sv.bias=vb; sv.C=g_vmix; sv.N=CD; sv.K=32;  sv.epi=EPI_VMIX;
        sv.p1=g_vraw; sv.p2=vfirst;
        sg.A=h_g; sg.B=rgB; sg.C=g_gate; sg.N=CD; sg.K=128; sg.epi=EPI_NONE;
        gemm_cp<<<dim3(CD/128, CM/128, 4), 256, SMEM>>>(sw, sa, sv, sg);
    }

    prep_kernel<<<CM*CH/8, 256>>>(g_kraw, g_iclr, k_k, k_a, g_kk, g_km, g_b);

    scan_kernel<<<CB*CH, 128>>>(g_r, g_w, g_km, g_vmix, g_kk, g_b, g_y);

    post_kernel<<<CM*CH/8, 256>>>(g_y, g_r, g_km, g_vmix, g_gate, gnw, gnb, r_k, g_pre);

    {
        Seg so=z;
        so.A=g_pre; so.B=rWo; so.C=out; so.N=CD; so.K=CD;
        gemm_cp<<<dim3(CD/128, CM/128, 1), 256, SMEM>>>(so, so, so, so);
    }
}

// round 6
// speedup vs baseline: 2.2801x; 1.2639x over previous
#include <cuda_runtime.h>
#include <cuda_bf16.h>
#include <math.h>
#include <stdint.h>

// Problem constants
#define CB 4
#define CL 2048
#define CD 1024
#define CH 16
#define CDh 64
#define CM (CB*CL)          // 8192 rows
#define MDSZ (8388608)      // CM*CD elements per scratch plane

__device__ float g_scratch[20ull*MDSZ];

enum { EPI_NONE=0, EPI_TANH=1, EPI_SIG=2, EPI_SIGBIAS=3, EPI_W=4, EPI_VMIX=5,
       EPI_KK=6, EPI_ICLRKMB=7 };

__device__ __forceinline__ float sigmoidf_(float x){ return 1.f/(1.f+expf(-x)); }

__device__ __forceinline__ uint32_t to_tf32(float f){
    uint32_t u; asm("cvt.rna.tf32.f32 %0, %1;" : "=r"(u) : "f"(f)); return u;
}
__device__ __forceinline__ float rnaf(float f){ return __uint_as_float(to_tf32(f)); }

__device__ __forceinline__ void mma_tf32(float* c, const uint32_t* a, uint32_t b0, uint32_t b1){
    asm volatile(
        "mma.sync.aligned.m16n8k8.row.col.f32.tf32.tf32.f32 "
        "{%0,%1,%2,%3}, {%4,%5,%6,%7}, {%8,%9}, {%0,%1,%2,%3};"
        : "+f"(c[0]), "+f"(c[1]), "+f"(c[2]), "+f"(c[3])
        : "r"(a[0]), "r"(a[1]), "r"(a[2]), "r"(a[3]), "r"(b0), "r"(b1));
}

// ---------------- prepare: token-shift mix (6 planes) + weight rounding ----------------
struct RW12 { const float* s[12]; float* d[12]; int n[12]; };
#define NB_MIX 8192

__global__ void __launch_bounds__(256) prepare_kernel(
    const float* __restrict__ x,
    const float* __restrict__ m0, const float* __restrict__ m1,
    const float* __restrict__ m2, const float* __restrict__ m3,
    const float* __restrict__ m4, const float* __restrict__ m5,
    float* __restrict__ o0, float* __restrict__ o1, float* __restrict__ o2,
    float* __restrict__ o3, float* __restrict__ o4, float* __restrict__ o5,
    RW12 w)
{
    if (blockIdx.x < NB_MIX) {
        size_t v = (size_t)blockIdx.x*256 + threadIdx.x;
        int m = (int)(v >> 8);
        int kp = (int)(v & 255) << 2;
        size_t off = (size_t)m*CD + kp;
        float4 xv = *(const float4*)(x + off);
        float4 xp = make_float4(0.f,0.f,0.f,0.f);
        if (m % CL) xp = *(const float4*)(x + off - CD);
        float4 dx = make_float4(xp.x-xv.x, xp.y-xv.y, xp.z-xv.z, xp.w-xv.w);
        #define DO_MIX(MI, OI) { \
            float4 mx = *(const float4*)(MI + kp); \
            float4 r; \
            r.x = rnaf(fmaf(dx.x, mx.x, xv.x)); \
            r.y = rnaf(fmaf(dx.y, mx.y, xv.y)); \
            r.z = rnaf(fmaf(dx.z, mx.z, xv.z)); \
            r.w = rnaf(fmaf(dx.w, mx.w, xv.w)); \
            *(float4*)(OI + off) = r; }
        DO_MIX(m0, o0); DO_MIX(m1, o1); DO_MIX(m2, o2);
        DO_MIX(m3, o3); DO_MIX(m4, o4); DO_MIX(m5, o5);
        #undef DO_MIX
    } else {
        int bb = blockIdx.x - NB_MIX;
        int seg = bb >> 6, sb = bb & 63;
        int n4 = w.n[seg] >> 2;
        const float* s = w.s[seg];
        float* d = w.d[seg];
        for (int v = sb*256 + threadIdx.x; v < n4; v += 64*256) {
            float4 a = *(const float4*)(s + v*4);
            float4 r = make_float4(rnaf(a.x), rnaf(a.y), rnaf(a.z), rnaf(a.w));
            *(float4*)(d + v*4) = r;
        }
    }
}

// ---------------- cp.async double-buffered tf32 GEMM, multi-segment ----------------
struct Seg {
    const float* A; const float* B; const float* bias;
    const float* p1; const float* p2; const float* p3;
    float* C; float* C2;
    int N; int K; int epi; int rnd; int gx;
};
struct Params7 { Seg s[7]; };

__global__ void __launch_bounds__(256,2) gemm_cp(Params7 P)
{
    extern __shared__ float sm[];
    Seg sg = P.s[blockIdx.z];
    if (blockIdx.x >= sg.gx) return;
    const int tid = threadIdx.x, lane = tid & 31, wid = tid >> 5;
    const int bm = blockIdx.y*128, bn = blockIdx.x*128;
    const int wm = (wid & 3)*32, wn = (wid >> 2)*64;
    const int K = sg.K, N = sg.N;

    float acc[2][8][4];
    #pragma unroll
    for (int i=0;i<2;i++)
        #pragma unroll
        for (int j=0;j<8;j++)
            #pragma unroll
            for (int q=0;q<4;q++) acc[i][j][q]=0.f;

    uint32_t smbase = (uint32_t)__cvta_generic_to_shared(sm);
    int nch = K >> 5;

    #define LOAD_CHUNK(c, st) { \
        int k0 = (c) << 5; \
        uint32_t ab = smbase + (uint32_t)(st)*9216u*4u; \
        uint32_t bb = ab + 4608u*4u; \
        _Pragma("unroll") \
        for (int i=0;i<4;i++){ \
            int v = i*256 + tid; \
            int row = v >> 3, c16 = v & 7; \
            const float* asrc = sg.A + (size_t)(bm+row)*K + k0 + c16*4; \
            uint32_t adst = ab + (uint32_t)(row*36 + c16*4)*4u; \
            asm volatile("cp.async.cg.shared.global [%0], [%1], 16;\n" :: "r"(adst), "l"(asrc)); \
            int n = bn + row; \
            const float* bsrc = sg.B + (size_t)n*K + k0 + c16*4; \
            uint32_t bdst = bb + (uint32_t)(row*36 + c16*4)*4u; \
            int szb = (n < N) ? 16 : 0; \
            asm volatile("cp.async.cg.shared.global [%0], [%1], 16, %2;\n" :: "r"(bdst), "l"(bsrc), "r"(szb)); \
        } \
        asm volatile("cp.async.commit_group;\n" ::: "memory"); }

    LOAD_CHUNK(0, 0);
    for (int c = 0; c < nch; c++) {
        int cur = c & 1;
        if (c + 1 < nch) {
            LOAD_CHUNK(c+1, (c+1)&1);
            asm volatile("cp.async.wait_group 1;\n" ::: "memory");
        } else {
            asm volatile("cp.async.wait_group 0;\n" ::: "memory");
        }
        __syncthreads();

        const float* As_ = sm + cur*9216;
        const float* Bs_ = As_ + 4608;
        #pragma unroll
        for (int s = 0; s < 4; s++) {
            int ks = (s << 3) + (lane & 3);
            uint32_t a[2][4];
            #pragma unroll
            for (int i = 0; i < 2; i++) {
                int r = wm + i*16 + (lane >> 2);
                a[i][0] = __float_as_uint(As_[r*36 + ks]);
                a[i][1] = __float_as_uint(As_[(r+8)*36 + ks]);
                a[i][2] = __float_as_uint(As_[r*36 + ks + 4]);
                a[i][3] = __float_as_uint(As_[(r+8)*36 + ks + 4]);
            }
            #pragma unroll
            for (int j = 0; j < 8; j++) {
                int n = wn + j*8 + (lane >> 2);
                uint32_t b0 = __float_as_uint(Bs_[n*36 + ks]);
                uint32_t b1 = __float_as_uint(Bs_[n*36 + ks + 4]);
                mma_tf32(acc[0][j], a[0], b0, b1);
                mma_tf32(acc[1][j], a[1], b0, b1);
            }
        }
        __syncthreads();
    }
    #undef LOAD_CHUNK

    int epi = sg.epi, rnd = sg.rnd;

    if (epi == EPI_KK) {
        // k projection epilogue: write kraw AND normalized kk (64-wide per-head norm)
        #pragma unroll
        for (int i = 0; i < 2; i++) {
            #pragma unroll
            for (int h = 0; h < 2; h++) {
                int m = bm + wm + i*16 + (lane >> 2) + h*8;
                float kkv[16];
                float ss = 0.f;
                #pragma unroll
                for (int j = 0; j < 8; j++) {
                    int col = bn + wn + j*8 + (lane & 3)*2;
                    float q0 = acc[i][j][h*2+0] * sg.p1[col];
                    float q1 = acc[i][j][h*2+1] * sg.p1[col+1];
                    kkv[j*2] = q0; kkv[j*2+1] = q1;
                    ss += q0*q0 + q1*q1;
                }
                ss += __shfl_xor_sync(0xffffffffu, ss, 1);
                ss += __shfl_xor_sync(0xffffffffu, ss, 2);
                float inv = 1.f / fmaxf(sqrtf(ss), 1e-7f);
                #pragma unroll
                for (int j = 0; j < 8; j++) {
                    int col = bn + wn + j*8 + (lane & 3)*2;
                    size_t idx = (size_t)m*N + col;
                    *(float2*)(sg.C  + idx) = make_float2(acc[i][j][h*2], acc[i][j][h*2+1]);
                    *(float2*)(sg.C2 + idx) = make_float2(kkv[j*2]*inv, kkv[j*2+1]*inv);
                }
            }
        }
        return;
    }

    #pragma unroll
    for (int i = 0; i < 2; i++) {
        int r0 = bm + wm + i*16 + (lane >> 2);
        #pragma unroll
        for (int j = 0; j < 8; j++) {
            int col = bn + wn + j*8 + (lane & 3)*2;
            if (col >= N) continue;
            #pragma unroll
            for (int h = 0; h < 2; h++) {
                int m = r0 + h*8;
                size_t idx = (size_t)m*N + col;
                float v0 = acc[i][j][h*2+0];
                float v1 = acc[i][j][h*2+1];
                if (epi == EPI_TANH) { v0 = tanhf(v0); v1 = tanhf(v1); }
                else if (epi == EPI_SIG) { v0 = sigmoidf_(v0); v1 = sigmoidf_(v1); }
                else if (epi == EPI_SIGBIAS) {
                    v0 = sigmoidf_(v0 + sg.bias[col]); v1 = sigmoidf_(v1 + sg.bias[col+1]);
                } else if (epi == EPI_W) {
                    v0 = expf(-0.606531f * sigmoidf_(v0 + sg.bias[col]));
                    v1 = expf(-0.606531f * sigmoidf_(v1 + sg.bias[col+1]));
                } else if (epi == EPI_VMIX) {
                    float t0 = sigmoidf_(v0 + sg.bias[col]), t1 = sigmoidf_(v1 + sg.bias[col+1]);
                    float2 vr = *(const float2*)(sg.p1 + idx);
                    float2 vf = *(const float2*)(sg.p2 + idx);
                    v0 = vr.x + (vf.x - vr.x)*t0;
                    v1 = vr.y + (vf.y - vr.y)*t1;
                } else if (epi == EPI_ICLRKMB) {
                    // iclr = sigmoid(acc+bias); km = kraw*(1+(iclr-1)*k_a); b = kk*iclr
                    float i0 = sigmoidf_(v0 + sg.bias[col]);
                    float i1 = sigmoidf_(v1 + sg.bias[col+1]);
                    float2 kr = *(const float2*)(sg.p1 + idx);
                    float2 kq = *(const float2*)(sg.p2 + idx);
                    float ka0 = sg.p3[col], ka1 = sg.p3[col+1];
                    v0 = kr.x * (1.f + (i0 - 1.f)*ka0);
                    v1 = kr.y * (1.f + (i1 - 1.f)*ka1);
                    *(float2*)(sg.C2 + idx) = make_float2(kq.x*i0, kq.y*i1);
                }
                if (rnd) { v0 = rnaf(v0); v1 = rnaf(v1); }
                *(float2*)(sg.C + idx) = make_float2(v0, v1);
            }
        }
    }
}

// ---------------- elementwise helpers ----------------
__device__ __forceinline__ float warp_red(float v) {
    #pragma unroll
    for (int s=16; s; s>>=1) v += __shfl_xor_sync(0xffffffffu, v, s);
    return v;
}

// ---------------- WKV7 scan: 256 threads, column quarters, 4-deep prefetch ----------------
// 8 warps. Warp w: quarter q = w>>1 (16 cols), state row = (w&1)*32+lane.
__global__ void __launch_bounds__(256,1) scan_kernel(
    const float* __restrict__ r, const float* __restrict__ w,
    const float* __restrict__ k, const float* __restrict__ v,
    const float* __restrict__ kkv, const float* __restrict__ bv,
    float* __restrict__ y)
{
    int bh = blockIdx.x;
    int b = bh >> 4, h = bh & 15;
    int tid = threadIdx.x;
    int lane = tid & 31, wid = tid >> 5;
    int quar = wid >> 1;                 // column quarter 0..3
    int row = ((wid & 1) << 5) + lane;   // state row 0..63
    int cb = quar << 4;                  // column base (16 cols)
    int j0 = tid & 63, grp = tid >> 6;   // staging role: grp 0..3 (grp3 idle)

    __shared__ float sh[2][6][64];       // 0=r 1=w 2=k 3=v 4=a(kk) 5=b
    __shared__ float dotbuf[4][64];
    __shared__ float ybuf[2][3][64];

    float4 S[4];
    #pragma unroll
    for (int q=0;q<4;q++) S[q] = make_float4(0.f,0.f,0.f,0.f);

    size_t base = (size_t)b*CL*CD + (size_t)h*CDh;

    const float* P0 = nullptr; const float* P1 = nullptr;
    int a0 = 0;
    if (grp == 0)      { P0 = r;   P1 = w;  a0 = 0; }
    else if (grp == 1) { P0 = k;   P1 = v;  a0 = 2; }
    else if (grp == 2) { P0 = kkv; P1 = bv; a0 = 4; }

    float pf[4][2];
    if (grp < 3) {
        #pragma unroll
        for (int d = 0; d < 4; d++) {
            size_t o = base + (size_t)d*CD + j0;
            pf[d][0] = P0[o]; pf[d][1] = P1[o];
        }
    }

    float ypPrev = 0.f;

    for (int t = 0; t < CL; t++) {
        int slot = t & 3, s = t & 1;
        if (grp < 3) {
            sh[s][a0][j0]   = pf[slot][0];
            sh[s][a0+1][j0] = pf[slot][1];
        }
        __syncthreads();   // barrier 1

        if (quar == 0 && t > 0) {
            y[base + (size_t)(t-1)*CD + row] =
                ypPrev + ybuf[s^1][0][row] + ybuf[s^1][1][row] + ybuf[s^1][2][row];
        }
        if (grp < 3 && t + 4 < CL) {
            size_t o = base + (size_t)(t+4)*CD + j0;
            pf[slot][0] = P0[o]; pf[slot][1] = P1[o];
        }

        // phase A: partial dot over this quarter's 16 columns
        {
            float d0=0.f,d1=0.f,d2=0.f,d3=0.f;
            #pragma unroll
            for (int q=0;q<4;q++) {
                float4 aq = *(const float4*)&sh[s][4][cb + (q<<2)];
                d0 += S[q].x*aq.x; d1 += S[q].y*aq.y;
                d2 += S[q].z*aq.z; d3 += S[q].w*aq.w;
            }
            dotbuf[quar][row] = (d0+d1)+(d2+d3);
        }
        __syncthreads();   // barrier 2

        {
            float sa = -((dotbuf[0][row] + dotbuf[1][row]) + (dotbuf[2][row] + dotbuf[3][row]));
            float vi = sh[s][3][row];
            float y0=0.f,y1=0.f,y2=0.f,y3=0.f;
            #pragma unroll
            for (int q=0;q<4;q++) {
                int c4 = cb + (q<<2);
                float4 wq = *(const float4*)&sh[s][1][c4];
                float4 kq = *(const float4*)&sh[s][2][c4];
                float4 bq = *(const float4*)&sh[s][5][c4];
                float4 rq = *(const float4*)&sh[s][0][c4];
                S[q].x = S[q].x*wq.x + vi*kq.x + sa*bq.x; y0 += S[q].x*rq.x;
                S[q].y = S[q].y*wq.y + vi*kq.y + sa*bq.y; y1 += S[q].y*rq.y;
                S[q].z = S[q].z*wq.z + vi*kq.z + sa*bq.z; y2 += S[q].z*rq.z;
                S[q].w = S[q].w*wq.w + vi*kq.w + sa*bq.w; y3 += S[q].w*rq.w;
            }
            float yp = (y0+y1)+(y2+y3);
            if (quar) ybuf[s][quar-1][row] = yp;
            else      ypPrev = yp;
        }
    }

    __syncthreads();
    if (quar == 0) {
        int s = (CL-1) & 1;
        y[base + (size_t)(CL-1)*CD + row] =
            ypPrev + ybuf[s][0][row] + ybuf[s][1][row] + ybuf[s][2][row];
    }
}

__global__ void post_kernel(const float* __restrict__ y, const float* __restrict__ r,
                            const float* __restrict__ kmod, const float* __restrict__ vmix,
                            const float* __restrict__ gate, const float* __restrict__ gnw,
                            const float* __restrict__ gnb, const float* __restrict__ r_k,
                            float* __restrict__ pre)
{
    int warp = threadIdx.x >> 5, lane = threadIdx.x & 31;
    int row = blockIdx.x*8 + warp;
    int m = row >> 4, h = row & 15;
    size_t off = (size_t)m*CD + h*CDh;
    int hh = h*CDh;

    float y1 = y[off+lane], y2 = y[off+32+lane];
    float mean = warp_red(y1 + y2) * (1.f/64.f);
    float d1 = y1 - mean, d2 = y2 - mean;
    float var = warp_red(d1*d1 + d2*d2) * (1.f/64.f);
    float inv = 1.f / sqrtf(var + 0.00064f);
    float o1 = gnw[hh+lane]   *d1*inv + gnb[hh+lane];
    float o2 = gnw[hh+32+lane]*d2*inv + gnb[hh+32+lane];

    float bonus = warp_red(r[off+lane]*kmod[off+lane]*r_k[hh+lane]
                         + r[off+32+lane]*kmod[off+32+lane]*r_k[hh+32+lane]);
    o1 += bonus * vmix[off+lane];
    o2 += bonus * vmix[off+32+lane];
    pre[off+lane]    = rnaf(o1 * gate[off+lane]);
    pre[off+32+lane] = rnaf(o2 * gate[off+32+lane]);
}

// ---------------- host ----------------
extern "C" void kernel_launch(void* const* d_in, const int* in_sizes, int n_in,
                              void* d_out, int out_size)
{
    const float* x      = (const float*)d_in[0];
    const float* vfirst = (const float*)d_in[1];
    const float* x_r    = (const float*)d_in[2];
    const float* x_w    = (const float*)d_in[3];
    const float* x_k    = (const float*)d_in[4];
    const float* x_v    = (const float*)d_in[5];
    const float* x_a    = (const float*)d_in[6];
    const float* x_g    = (const float*)d_in[7];
    const float* k_k    = (const float*)d_in[8];
    const float* k_a    = (const float*)d_in[9];
    const float* r_k    = (const float*)d_in[10];
    const float* Wr     = (const float*)d_in[11];
    const float* Wk     = (const float*)d_in[12];
    const float* Wv     = (const float*)d_in[13];
    const float* Wo     = (const float*)d_in[14];
    const float* gnw    = (const float*)d_in[15];
    const float* gnb    = (const float*)d_in[16];
    const float* wA     = (const float*)d_in[17];
    const float* wB     = (const float*)d_in[18];
    const float* wb     = (const float*)d_in[19];
    const float* vA     = (const float*)d_in[20];
    const float* vB     = (const float*)d_in[21];
    const float* vb     = (const float*)d_in[22];
    const float* aA     = (const float*)d_in[23];
    const float* aB     = (const float*)d_in[24];
    const float* ab     = (const float*)d_in[25];
    const float* gA     = (const float*)d_in[26];
    const float* gB     = (const float*)d_in[27];
    float* out = (float*)d_out;

    float* S;
    cudaGetSymbolAddress((void**)&S, g_scratch);
    float* p_xr   = S + 0ull*MDSZ;
    float* p_xw   = S + 1ull*MDSZ;
    float* p_xk   = S + 2ull*MDSZ;
    float* p_xv   = S + 3ull*MDSZ;
    float* p_xa   = S + 4ull*MDSZ;
    float* p_xg   = S + 5ull*MDSZ;
    float* g_r    = S + 6ull*MDSZ;
    float* g_kraw = S + 7ull*MDSZ;
    float* g_vraw = S + 8ull*MDSZ;
    float* g_w    = S + 9ull*MDSZ;
    float* g_vmix = S + 11ull*MDSZ;
    float* g_gate = S + 12ull*MDSZ;
    float* g_kk   = S + 13ull*MDSZ;
    float* g_km   = S + 14ull*MDSZ;
    float* g_b    = S + 15ull*MDSZ;
    float* g_y    = S + 16ull*MDSZ;
    float* g_pre  = S + 17ull*MDSZ;
    float* WBUF   = S + 18ull*MDSZ;
    float* HBUF   = S + 19ull*MDSZ;

    float* rWr = WBUF + 0;
    float* rWk = WBUF + 1048576;
    float* rWv = WBUF + 2097152;
    float* rWo = WBUF + 3145728;
    float* rwA = WBUF + 4194304;
    float* raA = WBUF + 4259840;
    float* rvA = WBUF + 4325376;
    float* rgA = WBUF + 4358144;
    float* rwB = WBUF + 4489216;
    float* raB = WBUF + 4554752;
    float* rvB = WBUF + 4620288;
    float* rgB = WBUF + 4653056;

    float* h_w = HBUF + 0;
    float* h_a = HBUF + 524288;
    float* h_v = HBUF + 1048576;
    float* h_g = HBUF + 1310720;

    const int SMEM = 2*9216*4;
    cudaFuncSetAttribute(gemm_cp, cudaFuncAttributeMaxDynamicSharedMemorySize, SMEM);

    // ---- launch 1: prepare (mix6 + weight rounding) ----
    {
        RW12 rw;
        const float* srcs[12] = {Wr,Wk,Wv,Wo, wA,aA,vA,gA, wB,aB,vB,gB};
        float* dsts[12] = {rWr,rWk,rWv,rWo, rwA,raA,rvA,rgA, rwB,raB,rvB,rgB};
        int ns[12] = {1048576,1048576,1048576,1048576, 65536,65536,32768,131072,
                      65536,65536,32768,131072};
        for (int i=0;i<12;i++){ rw.s[i]=srcs[i]; rw.d[i]=dsts[i]; rw.n[i]=ns[i]; }
        prepare_kernel<<<NB_MIX + 12*64, 256>>>(x, x_r, x_w, x_k, x_v, x_a, x_g,
                                                p_xr, p_xw, p_xk, p_xv, p_xa, p_xg, rw);
    }

    Seg z; z.A=nullptr; z.B=nullptr; z.bias=nullptr; z.p1=nullptr; z.p2=nullptr;
    z.p3=nullptr; z.C=nullptr; z.C2=nullptr; z.N=0; z.K=0; z.epi=EPI_NONE; z.rnd=0; z.gx=0;

    // ---- launch 2: big projections (r,k+kk,v) + all 4 LoRA stage-1, 7 segments ----
    {
        Params7 P;
        for (int i=0;i<7;i++) P.s[i] = z;
        P.s[0].A=p_xr; P.s[0].B=rWr; P.s[0].C=g_r;    P.s[0].N=CD; P.s[0].K=CD; P.s[0].gx=8;
        P.s[1].A=p_xk; P.s[1].B=rWk; P.s[1].C=g_kraw; P.s[1].N=CD; P.s[1].K=CD; P.s[1].gx=8;
        P.s[1].epi=EPI_KK; P.s[1].p1=k_k; P.s[1].C2=g_kk;
        P.s[2].A=p_xv; P.s[2].B=rWv; P.s[2].C=g_vraw; P.s[2].N=CD; P.s[2].K=CD; P.s[2].gx=8;
        P.s[3].A=p_xw; P.s[3].B=rwA; P.s[3].C=h_w; P.s[3].N=64;  P.s[3].K=CD; P.s[3].epi=EPI_TANH; P.s[3].rnd=1; P.s[3].gx=1;
        P.s[4].A=p_xa; P.s[4].B=raA; P.s[4].C=h_a; P.s[4].N=64;  P.s[4].K=CD; P.s[4].rnd=1; P.s[4].gx=1;
        P.s[5].A=p_xv; P.s[5].B=rvA; P.s[5].C=h_v; P.s[5].N=32;  P.s[5].K=CD; P.s[5].rnd=1; P.s[5].gx=1;
        P.s[6].A=p_xg; P.s[6].B=rgA; P.s[6].C=h_g; P.s[6].N=128; P.s[6].K=CD; P.s[6].epi=EPI_SIG; P.s[6].rnd=1; P.s[6].gx=1;
        gemm_cp<<<dim3(8, CM/128, 7), 256, SMEM>>>(P);
    }

    // ---- launch 3: LoRA stage-2 (w, iclr->km/b fused, vmix, gate), 4 segments ----
    {
        Params7 P;
        for (int i=0;i<7;i++) P.s[i] = z;
        P.s[0].A=h_w; P.s[0].B=rwB; P.s[0].bias=wb; P.s[0].C=g_w;  P.s[0].N=CD; P.s[0].K=64;  P.s[0].epi=EPI_W; P.s[0].gx=8;
        P.s[1].A=h_a; P.s[1].B=raB; P.s[1].bias=ab; P.s[1].C=g_km; P.s[1].N=CD; P.s[1].K=64;  P.s[1].epi=EPI_ICLRKMB; P.s[1].gx=8;
        P.s[1].p1=g_kraw; P.s[1].p2=g_kk; P.s[1].p3=k_a; P.s[1].C2=g_b;
        P.s[2].A=h_v; P.s[2].B=rvB; P.s[2].bias=vb; P.s[2].C=g_vmix; P.s[2].N=CD; P.s[2].K=32; P.s[2].epi=EPI_VMIX; P.s[2].gx=8;
        P.s[2].p1=g_vraw; P.s[2].p2=vfirst;
        P.s[3].A=h_g; P.s[3].B=rgB; P.s[3].C=g_gate; P.s[3].N=CD; P.s[3].K=128; P.s[3].gx=8;
        gemm_cp<<<dim3(8, CM/128, 4), 256, SMEM>>>(P);
    }

    // ---- launch 4: WKV7 scan (profiled slot) ----
    scan_kernel<<<CB*CH, 256>>>(g_r, g_w, g_km, g_vmix, g_kk, g_b, g_y);

    // ---- launch 5: groupnorm + bonus + gate ----
    post_kernel<<<CM*CH/8, 256>>>(g_y, g_r, g_km, g_vmix, g_gate, gnw, gnb, r_k, g_pre);

    // ---- launch 6: output projection ----
    {
        Params7 P;
        for (int i=0;i<7;i++) P.s[i] = z;
        P.s[0].A=g_pre; P.s[0].B=rWo; P.s[0].C=out; P.s[0].N=CD; P.s[0].K=CD; P.s[0].gx=8;
        gemm_cp<<<dim3(8, CM/128, 1), 256, SMEM>>>(P);
    }
}

// round 7
// speedup vs baseline: 3.2924x; 1.4440x over previous
#include <cuda_runtime.h>
#include <cuda_bf16.h>
#include <math.h>
#include <stdint.h>

// Problem constants
#define CB 4
#define CL 2048
#define CD 1024
#define CH 16
#define CDh 64
#define CM (CB*CL)          // 8192 rows
#define MDSZ (8388608)      // CM*CD elements per scratch plane

__device__ float g_scratch[20ull*MDSZ];

enum { EPI_NONE=0, EPI_TANH=1, EPI_SIG=2, EPI_SIGBIAS=3, EPI_W=4, EPI_VMIX=5,
       EPI_KK=6, EPI_ICLRKMB=7 };

__device__ __forceinline__ float sigmoidf_(float x){ return 1.f/(1.f+expf(-x)); }

__device__ __forceinline__ uint32_t to_tf32(float f){
    uint32_t u; asm("cvt.rna.tf32.f32 %0, %1;" : "=r"(u) : "f"(f)); return u;
}
__device__ __forceinline__ float rnaf(float f){ return __uint_as_float(to_tf32(f)); }

__device__ __forceinline__ void mma_tf32(float* c, const uint32_t* a, uint32_t b0, uint32_t b1){
    asm volatile(
        "mma.sync.aligned.m16n8k8.row.col.f32.tf32.tf32.f32 "
        "{%0,%1,%2,%3}, {%4,%5,%6,%7}, {%8,%9}, {%0,%1,%2,%3};"
        : "+f"(c[0]), "+f"(c[1]), "+f"(c[2]), "+f"(c[3])
        : "r"(a[0]), "r"(a[1]), "r"(a[2]), "r"(a[3]), "r"(b0), "r"(b1));
}

// ---------------- prepare: token-shift mix (6 planes) + weight rounding ----------------
struct RW12 { const float* s[12]; float* d[12]; int n[12]; };
#define NB_MIX 8192

__global__ void __launch_bounds__(256) prepare_kernel(
    const float* __restrict__ x,
    const float* __restrict__ m0, const float* __restrict__ m1,
    const float* __restrict__ m2, const float* __restrict__ m3,
    const float* __restrict__ m4, const float* __restrict__ m5,
    float* __restrict__ o0, float* __restrict__ o1, float* __restrict__ o2,
    float* __restrict__ o3, float* __restrict__ o4, float* __restrict__ o5,
    RW12 w)
{
    if (blockIdx.x < NB_MIX) {
        size_t v = (size_t)blockIdx.x*256 + threadIdx.x;
        int m = (int)(v >> 8);
        int kp = (int)(v & 255) << 2;
        size_t off = (size_t)m*CD + kp;
        float4 xv = *(const float4*)(x + off);
        float4 xp = make_float4(0.f,0.f,0.f,0.f);
        if (m % CL) xp = *(const float4*)(x + off - CD);
        float4 dx = make_float4(xp.x-xv.x, xp.y-xv.y, xp.z-xv.z, xp.w-xv.w);
        #define DO_MIX(MI, OI) { \
            float4 mx = *(const float4*)(MI + kp); \
            float4 r; \
            r.x = rnaf(fmaf(dx.x, mx.x, xv.x)); \
            r.y = rnaf(fmaf(dx.y, mx.y, xv.y)); \
            r.z = rnaf(fmaf(dx.z, mx.z, xv.z)); \
            r.w = rnaf(fmaf(dx.w, mx.w, xv.w)); \
            *(float4*)(OI + off) = r; }
        DO_MIX(m0, o0); DO_MIX(m1, o1); DO_MIX(m2, o2);
        DO_MIX(m3, o3); DO_MIX(m4, o4); DO_MIX(m5, o5);
        #undef DO_MIX
    } else {
        int bb = blockIdx.x - NB_MIX;
        int seg = bb >> 6, sb = bb & 63;
        int n4 = w.n[seg] >> 2;
        const float* s = w.s[seg];
        float* d = w.d[seg];
        for (int v = sb*256 + threadIdx.x; v < n4; v += 64*256) {
            float4 a = *(const float4*)(s + v*4);
            float4 r = make_float4(rnaf(a.x), rnaf(a.y), rnaf(a.z), rnaf(a.w));
            *(float4*)(d + v*4) = r;
        }
    }
}

// ---------------- cp.async double-buffered tf32 GEMM, multi-segment ----------------
struct Seg {
    const float* A; const float* B; const float* bias;
    const float* p1; const float* p2; const float* p3;
    float* C; float* C2;
    int N; int K; int epi; int rnd; int gx;
};
struct Params7 { Seg s[7]; };

__global__ void __launch_bounds__(256,2) gemm_cp(Params7 P)
{
    extern __shared__ float sm[];
    Seg sg = P.s[blockIdx.z];
    if (blockIdx.x >= sg.gx) return;
    const int tid = threadIdx.x, lane = tid & 31, wid = tid >> 5;
    const int bm = blockIdx.y*128, bn = blockIdx.x*128;
    const int wm = (wid & 3)*32, wn = (wid >> 2)*64;
    const int K = sg.K, N = sg.N;

    float acc[2][8][4];
    #pragma unroll
    for (int i=0;i<2;i++)
        #pragma unroll
        for (int j=0;j<8;j++)
            #pragma unroll
            for (int q=0;q<4;q++) acc[i][j][q]=0.f;

    uint32_t smbase = (uint32_t)__cvta_generic_to_shared(sm);
    int nch = K >> 5;

    #define LOAD_CHUNK(c, st) { \
        int k0 = (c) << 5; \
        uint32_t ab = smbase + (uint32_t)(st)*9216u*4u; \
        uint32_t bb = ab + 4608u*4u; \
        _Pragma("unroll") \
        for (int i=0;i<4;i++){ \
            int v = i*256 + tid; \
            int row = v >> 3, c16 = v & 7; \
            const float* asrc = sg.A + (size_t)(bm+row)*K + k0 + c16*4; \
            uint32_t adst = ab + (uint32_t)(row*36 + c16*4)*4u; \
            asm volatile("cp.async.cg.shared.global [%0], [%1], 16;\n" :: "r"(adst), "l"(asrc)); \
            int n = bn + row; \
            const float* bsrc = sg.B + (size_t)n*K + k0 + c16*4; \
            uint32_t bdst = bb + (uint32_t)(row*36 + c16*4)*4u; \
            int szb = (n < N) ? 16 : 0; \
            asm volatile("cp.async.cg.shared.global [%0], [%1], 16, %2;\n" :: "r"(bdst), "l"(bsrc), "r"(szb)); \
        } \
        asm volatile("cp.async.commit_group;\n" ::: "memory"); }

    LOAD_CHUNK(0, 0);
    for (int c = 0; c < nch; c++) {
        int cur = c & 1;
        if (c + 1 < nch) {
            LOAD_CHUNK(c+1, (c+1)&1);
            asm volatile("cp.async.wait_group 1;\n" ::: "memory");
        } else {
            asm volatile("cp.async.wait_group 0;\n" ::: "memory");
        }
        __syncthreads();

        const float* As_ = sm + cur*9216;
        const float* Bs_ = As_ + 4608;
        #pragma unroll
        for (int s = 0; s < 4; s++) {
            int ks = (s << 3) + (lane & 3);
            uint32_t a[2][4];
            #pragma unroll
            for (int i = 0; i < 2; i++) {
                int r = wm + i*16 + (lane >> 2);
                a[i][0] = __float_as_uint(As_[r*36 + ks]);
                a[i][1] = __float_as_uint(As_[(r+8)*36 + ks]);
                a[i][2] = __float_as_uint(As_[r*36 + ks + 4]);
                a[i][3] = __float_as_uint(As_[(r+8)*36 + ks + 4]);
            }
            #pragma unroll
            for (int j = 0; j < 8; j++) {
                int n = wn + j*8 + (lane >> 2);
                uint32_t b0 = __float_as_uint(Bs_[n*36 + ks]);
                uint32_t b1 = __float_as_uint(Bs_[n*36 + ks + 4]);
                mma_tf32(acc[0][j], a[0], b0, b1);
                mma_tf32(acc[1][j], a[1], b0, b1);
            }
        }
        __syncthreads();
    }
    #undef LOAD_CHUNK

    int epi = sg.epi, rnd = sg.rnd;

    if (epi == EPI_KK) {
        #pragma unroll
        for (int i = 0; i < 2; i++) {
            #pragma unroll
            for (int h = 0; h < 2; h++) {
                int m = bm + wm + i*16 + (lane >> 2) + h*8;
                float kkv[16];
                float ss = 0.f;
                #pragma unroll
                for (int j = 0; j < 8; j++) {
                    int col = bn + wn + j*8 + (lane & 3)*2;
                    float q0 = acc[i][j][h*2+0] * sg.p1[col];
                    float q1 = acc[i][j][h*2+1] * sg.p1[col+1];
                    kkv[j*2] = q0; kkv[j*2+1] = q1;
                    ss += q0*q0 + q1*q1;
                }
                ss += __shfl_xor_sync(0xffffffffu, ss, 1);
                ss += __shfl_xor_sync(0xffffffffu, ss, 2);
                float inv = 1.f / fmaxf(sqrtf(ss), 1e-7f);
                #pragma unroll
                for (int j = 0; j < 8; j++) {
                    int col = bn + wn + j*8 + (lane & 3)*2;
                    size_t idx = (size_t)m*N + col;
                    *(float2*)(sg.C  + idx) = make_float2(acc[i][j][h*2], acc[i][j][h*2+1]);
                    *(float2*)(sg.C2 + idx) = make_float2(kkv[j*2]*inv, kkv[j*2+1]*inv);
                }
            }
        }
        return;
    }

    #pragma unroll
    for (int i = 0; i < 2; i++) {
        int r0 = bm + wm + i*16 + (lane >> 2);
        #pragma unroll
        for (int j = 0; j < 8; j++) {
            int col = bn + wn + j*8 + (lane & 3)*2;
            if (col >= N) continue;
            #pragma unroll
            for (int h = 0; h < 2; h++) {
                int m = r0 + h*8;
                size_t idx = (size_t)m*N + col;
                float v0 = acc[i][j][h*2+0];
                float v1 = acc[i][j][h*2+1];
                if (epi == EPI_TANH) { v0 = tanhf(v0); v1 = tanhf(v1); }
                else if (epi == EPI_SIG) { v0 = sigmoidf_(v0); v1 = sigmoidf_(v1); }
                else if (epi == EPI_SIGBIAS) {
                    v0 = sigmoidf_(v0 + sg.bias[col]); v1 = sigmoidf_(v1 + sg.bias[col+1]);
                } else if (epi == EPI_W) {
                    v0 = expf(-0.606531f * sigmoidf_(v0 + sg.bias[col]));
                    v1 = expf(-0.606531f * sigmoidf_(v1 + sg.bias[col+1]));
                } else if (epi == EPI_VMIX) {
                    float t0 = sigmoidf_(v0 + sg.bias[col]), t1 = sigmoidf_(v1 + sg.bias[col+1]);
                    float2 vr = *(const float2*)(sg.p1 + idx);
                    float2 vf = *(const float2*)(sg.p2 + idx);
                    v0 = vr.x + (vf.x - vr.x)*t0;
                    v1 = vr.y + (vf.y - vr.y)*t1;
                } else if (epi == EPI_ICLRKMB) {
                    float i0 = sigmoidf_(v0 + sg.bias[col]);
                    float i1 = sigmoidf_(v1 + sg.bias[col+1]);
                    float2 kr = *(const float2*)(sg.p1 + idx);
                    float2 kq = *(const float2*)(sg.p2 + idx);
                    float ka0 = sg.p3[col], ka1 = sg.p3[col+1];
                    v0 = kr.x * (1.f + (i0 - 1.f)*ka0);
                    v1 = kr.y * (1.f + (i1 - 1.f)*ka1);
                    *(float2*)(sg.C2 + idx) = make_float2(kq.x*i0, kq.y*i1);
                }
                if (rnd) { v0 = rnaf(v0); v1 = rnaf(v1); }
                *(float2*)(sg.C + idx) = make_float2(v0, v1);
            }
        }
    }
}

// ---------------- elementwise helpers ----------------
__device__ __forceinline__ float warp_red(float v) {
    #pragma unroll
    for (int s=16; s; s>>=1) v += __shfl_xor_sync(0xffffffffu, v, s);
    return v;
}

// ---------------- WKV7 scan: cp.async 8-stage ring, 256 threads ----------------
// 8 warps. Warp w: quarter q = w>>1 (16 cols), state row = (w&1)*32+lane.
// Threads 0..95 each stream one 16B slice of the 6x64-float step vector
// directly GMEM->smem ring via cp.async (depth 7 ahead) — no register path,
// so DRAM latency is fully hidden regardless of ptxas allocation.
__global__ void __launch_bounds__(256,1) scan_kernel(
    const float* __restrict__ r, const float* __restrict__ w,
    const float* __restrict__ k, const float* __restrict__ v,
    const float* __restrict__ kkv, const float* __restrict__ bv,
    float* __restrict__ y)
{
    int bh = blockIdx.x;
    int b = bh >> 4, h = bh & 15;
    int tid = threadIdx.x;
    int lane = tid & 31, wid = tid >> 5;
    int quar = wid >> 1;                 // column quarter 0..3
    int row = ((wid & 1) << 5) + lane;   // state row 0..63
    int cb = quar << 4;                  // column base (16 cols)

    __shared__ float ring[8][6][64];     // plane order: 0=r 1=w 2=k 3=v 4=a(kk) 5=b
    __shared__ float dotbuf[4][64];
    __shared__ float ybuf[2][3][64];

    size_t base = (size_t)b*CL*CD + (size_t)h*CDh;

    const bool ld = (tid < 96);
    const float* src = nullptr;
    uint32_t dst0 = 0;
    if (ld) {
        int c6 = tid >> 4;
        int j4 = (tid & 15) << 2;
        const float* planes[6] = {r, w, k, v, kkv, bv};
        src = planes[c6] + base + j4;
        dst0 = (uint32_t)__cvta_generic_to_shared(&ring[0][c6][j4]);
    }
    const uint32_t STG = 6*64*4;         // bytes per ring stage

    // preload 7 stages
    if (ld) {
        #pragma unroll
        for (int t = 0; t < 7; t++) {
            uint32_t d = dst0 + (uint32_t)t*STG;
            asm volatile("cp.async.cg.shared.global [%0], [%1], 16;\n"
                         :: "r"(d), "l"(src + (size_t)t*CD));
            asm volatile("cp.async.commit_group;\n" ::: "memory");
        }
    }

    float4 S[4];
    #pragma unroll
    for (int q=0;q<4;q++) S[q] = make_float4(0.f,0.f,0.f,0.f);
    float ypPrev = 0.f;

    for (int t = 0; t < CL; t++) {
        int st = t & 7, s = t & 1;
        if (ld) { asm volatile("cp.async.wait_group 6;\n" ::: "memory"); }
        __syncthreads();   // barrier 1: stage t visible; everyone done with t-1

        // complete y of step t-1
        if (quar == 0 && t > 0) {
            y[base + (size_t)(t-1)*CD + row] =
                ypPrev + ybuf[s^1][0][row] + ybuf[s^1][1][row] + ybuf[s^1][2][row];
        }
        // issue prefetch for stage t+7 (slot (t-1)&7, now free)
        if (ld) {
            if (t + 7 < CL) {
                uint32_t d = dst0 + (uint32_t)((t+7)&7)*STG;
                asm volatile("cp.async.cg.shared.global [%0], [%1], 16;\n"
                             :: "r"(d), "l"(src + (size_t)(t+7)*CD));
            }
            asm volatile("cp.async.commit_group;\n" ::: "memory");
        }

        // phase A: partial dot over this quarter's 16 columns
        {
            float d0=0.f,d1=0.f,d2=0.f,d3=0.f;
            #pragma unroll
            for (int q=0;q<4;q++) {
                float4 aq = *(const float4*)&ring[st][4][cb + (q<<2)];
                d0 += S[q].x*aq.x; d1 += S[q].y*aq.y;
                d2 += S[q].z*aq.z; d3 += S[q].w*aq.w;
            }
            dotbuf[quar][row] = (d0+d1)+(d2+d3);
        }
        __syncthreads();   // barrier 2: dot partials visible

        {
            float sa = -((dotbuf[0][row] + dotbuf[1][row]) + (dotbuf[2][row] + dotbuf[3][row]));
            float vi = ring[st][3][row];
            float y0=0.f,y1=0.f,y2=0.f,y3=0.f;
            #pragma unroll
            for (int q=0;q<4;q++) {
                int c4 = cb + (q<<2);
                float4 wq = *(const float4*)&ring[st][1][c4];
                float4 kq = *(const float4*)&ring[st][2][c4];
                float4 bq = *(const float4*)&ring[st][5][c4];
                float4 rq = *(const float4*)&ring[st][0][c4];
                S[q].x = S[q].x*wq.x + vi*kq.x + sa*bq.x; y0 += S[q].x*rq.x;
                S[q].y = S[q].y*wq.y + vi*kq.y + sa*bq.y; y1 += S[q].y*rq.y;
                S[q].z = S[q].z*wq.z + vi*kq.z + sa*bq.z; y2 += S[q].z*rq.z;
                S[q].w = S[q].w*wq.w + vi*kq.w + sa*bq.w; y3 += S[q].w*rq.w;
            }
            float yp = (y0+y1)+(y2+y3);
            if (quar) ybuf[s][quar-1][row] = yp;
            else      ypPrev = yp;
        }
    }

    __syncthreads();
    if (quar == 0) {
        int s = (CL-1) & 1;
        y[base + (size_t)(CL-1)*CD + row] =
            ypPrev + ybuf[s][0][row] + ybuf[s][1][row] + ybuf[s][2][row];
    }
}

__global__ void post_kernel(const float* __restrict__ y, const float* __restrict__ r,
                            const float* __restrict__ kmod, const float* __restrict__ vmix,
                            const float* __restrict__ gate, const float* __restrict__ gnw,
                            const float* __restrict__ gnb, const float* __restrict__ r_k,
                            float* __restrict__ pre)
{
    int warp = threadIdx.x >> 5, lane = threadIdx.x & 31;
    int row = blockIdx.x*8 + warp;
    int m = row >> 4, h = row & 15;
    size_t off = (size_t)m*CD + h*CDh;
    int hh = h*CDh;

    float y1 = y[off+lane], y2 = y[off+32+lane];
    float mean = warp_red(y1 + y2) * (1.f/64.f);
    float d1 = y1 - mean, d2 = y2 - mean;
    float var = warp_red(d1*d1 + d2*d2) * (1.f/64.f);
    float inv = 1.f / sqrtf(var + 0.00064f);
    float o1 = gnw[hh+lane]   *d1*inv + gnb[hh+lane];
    float o2 = gnw[hh+32+lane]*d2*inv + gnb[hh+32+lane];

    float bonus = warp_red(r[off+lane]*kmod[off+lane]*r_k[hh+lane]
                         + r[off+32+lane]*kmod[off+32+lane]*r_k[hh+32+lane]);
    o1 += bonus * vmix[off+lane];
    o2 += bonus * vmix[off+32+lane];
    pre[off+lane]    = rnaf(o1 * gate[off+lane]);
    pre[off+32+lane] = rnaf(o2 * gate[off+32+lane]);
}

// ---------------- host ----------------
extern "C" void kernel_launch(void* const* d_in, const int* in_sizes, int n_in,
                              void* d_out, int out_size)
{
    const float* x      = (const float*)d_in[0];
    const float* vfirst = (const float*)d_in[1];
    const float* x_r    = (const float*)d_in[2];
    const float* x_w    = (const float*)d_in[3];
    const float* x_k    = (const float*)d_in[4];
    const float* x_v    = (const float*)d_in[5];
    const float* x_a    = (const float*)d_in[6];
    const float* x_g    = (const float*)d_in[7];
    const float* k_k    = (const float*)d_in[8];
    const float* k_a    = (const float*)d_in[9];
    const float* r_k    = (const float*)d_in[10];
    const float* Wr     = (const float*)d_in[11];
    const float* Wk     = (const float*)d_in[12];
    const float* Wv     = (const float*)d_in[13];
    const float* Wo     = (const float*)d_in[14];
    const float* gnw    = (const float*)d_in[15];
    const float* gnb    = (const float*)d_in[16];
    const float* wA     = (const float*)d_in[17];
    const float* wB     = (const float*)d_in[18];
    const float* wb     = (const float*)d_in[19];
    const float* vA     = (const float*)d_in[20];
    const float* vB     = (const float*)d_in[21];
    const float* vb     = (const float*)d_in[22];
    const float* aA     = (const float*)d_in[23];
    const float* aB     = (const float*)d_in[24];
    const float* ab     = (const float*)d_in[25];
    const float* gA     = (const float*)d_in[26];
    const float* gB     = (const float*)d_in[27];
    float* out = (float*)d_out;

    float* S;
    cudaGetSymbolAddress((void**)&S, g_scratch);
    float* p_xr   = S + 0ull*MDSZ;
    float* p_xw   = S + 1ull*MDSZ;
    float* p_xk   = S + 2ull*MDSZ;
    float* p_xv   = S + 3ull*MDSZ;
    float* p_xa   = S + 4ull*MDSZ;
    float* p_xg   = S + 5ull*MDSZ;
    float* g_r    = S + 6ull*MDSZ;
    float* g_kraw = S + 7ull*MDSZ;
    float* g_vraw = S + 8ull*MDSZ;
    float* g_w    = S + 9ull*MDSZ;
    float* g_vmix = S + 11ull*MDSZ;
    float* g_gate = S + 12ull*MDSZ;
    float* g_kk   = S + 13ull*MDSZ;
    float* g_km   = S + 14ull*MDSZ;
    float* g_b    = S + 15ull*MDSZ;
    float* g_y    = S + 16ull*MDSZ;
    float* g_pre  = S + 17ull*MDSZ;
    float* WBUF   = S + 18ull*MDSZ;
    float* HBUF   = S + 19ull*MDSZ;

    float* rWr = WBUF + 0;
    float* rWk = WBUF + 1048576;
    float* rWv = WBUF + 2097152;
    float* rWo = WBUF + 3145728;
    float* rwA = WBUF + 4194304;
    float* raA = WBUF + 4259840;
    float* rvA = WBUF + 4325376;
    float* rgA = WBUF + 4358144;
    float* rwB = WBUF + 4489216;
    float* raB = WBUF + 4554752;
    float* rvB = WBUF + 4620288;
    float* rgB = WBUF + 4653056;

    float* h_w = HBUF + 0;
    float* h_a = HBUF + 524288;
    float* h_v = HBUF + 1048576;
    float* h_g = HBUF + 1310720;

    const int SMEM = 2*9216*4;
    cudaFuncSetAttribute(gemm_cp, cudaFuncAttributeMaxDynamicSharedMemorySize, SMEM);

    // ---- launch 1: prepare (mix6 + weight rounding) ----
    {
        RW12 rw;
        const float* srcs[12] = {Wr,Wk,Wv,Wo, wA,aA,vA,gA, wB,aB,vB,gB};
        float* dsts[12] = {rWr,rWk,rWv,rWo, rwA,raA,rvA,rgA, rwB,raB,rvB,rgB};
        int ns[12] = {1048576,1048576,1048576,1048576, 65536,65536,32768,131072,
                      65536,65536,32768,131072};
        for (int i=0;i<12;i++){ rw.s[i]=srcs[i]; rw.d[i]=dsts[i]; rw.n[i]=ns[i]; }
        prepare_kernel<<<NB_MIX + 12*64, 256>>>(x, x_r, x_w, x_k, x_v, x_a, x_g,
                                                p_xr, p_xw, p_xk, p_xv, p_xa, p_xg, rw);
    }

    Seg z; z.A=nullptr; z.B=nullptr; z.bias=nullptr; z.p1=nullptr; z.p2=nullptr;
    z.p3=nullptr; z.C=nullptr; z.C2=nullptr; z.N=0; z.K=0; z.epi=EPI_NONE; z.rnd=0; z.gx=0;

    // ---- launch 2: big projections (r,k+kk,v) + all 4 LoRA stage-1 ----
    {
        Params7 P;
        for (int i=0;i<7;i++) P.s[i] = z;
        P.s[0].A=p_xr; P.s[0].B=rWr; P.s[0].C=g_r;    P.s[0].N=CD; P.s[0].K=CD; P.s[0].gx=8;
        P.s[1].A=p_xk; P.s[1].B=rWk; P.s[1].C=g_kraw; P.s[1].N=CD; P.s[1].K=CD; P.s[1].gx=8;
        P.s[1].epi=EPI_KK; P.s[1].p1=k_k; P.s[1].C2=g_kk;
        P.s[2].A=p_xv; P.s[2].B=rWv; P.s[2].C=g_vraw; P.s[2].N=CD; P.s[2].K=CD; P.s[2].gx=8;
        P.s[3].A=p_xw; P.s[3].B=rwA; P.s[3].C=h_w; P.s[3].N=64;  P.s[3].K=CD; P.s[3].epi=EPI_TANH; P.s[3].rnd=1; P.s[3].gx=1;
        P.s[4].A=p_xa; P.s[4].B=raA; P.s[4].C=h_a; P.s[4].N=64;  P.s[4].K=CD; P.s[4].rnd=1; P.s[4].gx=1;
        P.s[5].A=p_xv; P.s[5].B=rvA; P.s[5].C=h_v; P.s[5].N=32;  P.s[5].K=CD; P.s[5].rnd=1; P.s[5].gx=1;
        P.s[6].A=p_xg; P.s[6].B=rgA; P.s[6].C=h_g; P.s[6].N=128; P.s[6].K=CD; P.s[6].epi=EPI_SIG; P.s[6].rnd=1; P.s[6].gx=1;
        gemm_cp<<<dim3(8, CM/128, 7), 256, SMEM>>>(P);
    }

    // ---- launch 3: LoRA stage-2 (w, iclr->km/b fused, vmix, gate) ----
    {
        Params7 P;
        for (int i=0;i<7;i++) P.s[i] = z;
        P.s[0].A=h_w; P.s[0].B=rwB; P.s[0].bias=wb; P.s[0].C=g_w;  P.s[0].N=CD; P.s[0].K=64;  P.s[0].epi=EPI_W; P.s[0].gx=8;
        P.s[1].A=h_a; P.s[1].B=raB; P.s[1].bias=ab; P.s[1].C=g_km; P.s[1].N=CD; P.s[1].K=64;  P.s[1].epi=EPI_ICLRKMB; P.s[1].gx=8;
        P.s[1].p1=g_kraw; P.s[1].p2=g_kk; P.s[1].p3=k_a; P.s[1].C2=g_b;
        P.s[2].A=h_v; P.s[2].B=rvB; P.s[2].bias=vb; P.s[2].C=g_vmix; P.s[2].N=CD; P.s[2].K=32; P.s[2].epi=EPI_VMIX; P.s[2].gx=8;
        P.s[2].p1=g_vraw; P.s[2].p2=vfirst;
        P.s[3].A=h_g; P.s[3].B=rgB; P.s[3].C=g_gate; P.s[3].N=CD; P.s[3].K=128; P.s[3].gx=8;
        gemm_cp<<<dim3(8, CM/128, 4), 256, SMEM>>>(P);
    }

    // ---- launch 4: WKV7 scan (profiled slot) ----
    scan_kernel<<<CB*CH, 256>>>(g_r, g_w, g_km, g_vmix, g_kk, g_b, g_y);

    // ---- launch 5: groupnorm + bonus + gate ----
    post_kernel<<<CM*CH/8, 256>>>(g_y, g_r, g_km, g_vmix, g_gate, gnw, gnb, r_k, g_pre);

    // ---- launch 6: output projection ----
    {
        Params7 P;
        for (int i=0;i<7;i++) P.s[i] = z;
        P.s[0].A=g_pre; P.s[0].B=rWo; P.s[0].C=out; P.s[0].N=CD; P.s[0].K=CD; P.s[0].gx=8;
        gemm_cp<<<dim3(8, CM/128, 1), 256, SMEM>>>(P);
    }
}